// round 1
// baseline (speedup 1.0000x reference)
#include <cuda_runtime.h>
#include <math.h>

#define B     16384
#define DIN   12
#define HLF   6
#define HID   192
#define LAYERS 24
#define NB    66

// ---------------- scratch (static device globals; no allocs) ----------------
__device__ float    g_zk[(LAYERS + 1) * B * DIN];   // z_k, k=0..24 (24 = y)
__device__ float    g_s [LAYERS * B * HLF];         // per-layer s
__device__ unsigned g_m1[LAYERS * B * 6];           // relu masks layer 1
__device__ unsigned g_m2[LAYERS * B * 6];           // relu masks layer 2
__device__ float    g_V [B * 6 * DIN];              // cotangent state (6x12/sample)
__device__ float    g_ld[B];                        // log-det accumulator
__device__ float    g_part[256];
__device__ float    g_ssq;

// ---------------- init ----------------
__global__ void k_init(const float* __restrict__ y, const float* __restrict__ Jp) {
    int i0 = blockIdx.x * blockDim.x + threadIdx.x;
    int st = gridDim.x * blockDim.x;
    for (int i = i0; i < B * 72; i += st) {
        g_V[i] = Jp[i];
        if (i < B * DIN) g_zk[LAYERS * B * DIN + i] = y[i];
        if (i < B)       g_ld[i] = 0.f;
    }
}

// ---------------- inverse coupling layer (stores z_k, s, masks) ----------------
__global__ void __launch_bounds__(256) k_inv_layer(
    const float* __restrict__ W1, const float* __restrict__ b1,
    const float* __restrict__ W2, const float* __restrict__ b2,
    const float* __restrict__ W3, const float* __restrict__ b3, int k)
{
    extern __shared__ float sm[];
    float* W1t = sm;                 // [6][192] transposed
    float* b1s = W1t + HLF * HID;    // 192
    float* W2t = b1s + HID;          // [192][193] transposed+pad
    float* b2s = W2t + HID * 193;    // 192
    float* W3s = b2s + HID;          // [12][192] row-major
    float* b3s = W3s + 12 * HID;     // 16
    float* h1s = b3s + 16;           // 8 warps * 192

    int tid = threadIdx.x;
    for (int i = tid; i < HLF * HID; i += 256) { int r = i / HLF, j = i % HLF; W1t[j * HID + r] = W1[i]; }
    for (int i = tid; i < HID; i += 256) { b1s[i] = b1[i]; b2s[i] = b2[i]; }
    for (int i = tid; i < HID * HID; i += 256) { int r = i / HID, j = i % HID; W2t[j * 193 + r] = W2[i]; }
    for (int i = tid; i < 12 * HID; i += 256) W3s[i] = W3[i];
    if (tid < 12) b3s[tid] = b3[tid];
    __syncthreads();

    int lane = tid & 31, wip = tid >> 5;
    float* h1w = h1s + wip * HID;
    int w  = (blockIdx.x * 256 + tid) >> 5;
    int nw = gridDim.x * 8;

    for (int b = w; b < B; b += nw) {
        const float* zin = g_zk + ((size_t)(k + 1) * B + b) * DIN;
        float z1[6], z2[6];
#pragma unroll
        for (int j = 0; j < 6; j++) { z1[j] = zin[6 + j]; z2[j] = zin[j]; }

        __syncwarp();
        unsigned mm1[6];
#pragma unroll
        for (int i = 0; i < 6; i++) {
            int r = lane + 32 * i;
            float a = b1s[r];
#pragma unroll
            for (int j = 0; j < 6; j++) a += W1t[j * HID + r] * z1[j];
            mm1[i] = __ballot_sync(0xffffffffu, a > 0.f);
            h1w[r] = fmaxf(a, 0.f);
        }
        __syncwarp();

        float h2a[6];
#pragma unroll
        for (int i = 0; i < 6; i++) h2a[i] = b2s[lane + 32 * i];
        const float* wp = W2t + lane;
        for (int j = 0; j < HID; j++) {
            float hj = h1w[j];
#pragma unroll
            for (int i = 0; i < 6; i++) h2a[i] += wp[j * 193 + 32 * i] * hj;
        }
        unsigned mm2[6];
#pragma unroll
        for (int i = 0; i < 6; i++) {
            mm2[i] = __ballot_sync(0xffffffffu, h2a[i] > 0.f);
            h2a[i] = fmaxf(h2a[i], 0.f);
        }

        float pp[12];
#pragma unroll
        for (int o = 0; o < 12; o++) {
            float a = 0.f;
#pragma unroll
            for (int i = 0; i < 6; i++) a += W3s[o * HID + lane + 32 * i] * h2a[i];
#pragma unroll
            for (int off = 16; off > 0; off >>= 1) a += __shfl_xor_sync(0xffffffffu, a, off);
            pp[o] = a;
        }

        float ssum = 0.f, sv[6], znew[6];
#pragma unroll
        for (int j = 0; j < 6; j++) {
            float sh = pp[2 * j] + b3s[2 * j];
            float sr = pp[2 * j + 1] + b3s[2 * j + 1];
            float s  = 2.f * tanhf(0.5f * sr);
            sv[j] = s; ssum += s;
            znew[j] = (z2[j] - sh) * expf(-s);
        }
        if (lane == 0) {
            float* zo = g_zk + ((size_t)k * B + b) * DIN;
#pragma unroll
            for (int j = 0; j < 6; j++) { zo[j] = z1[j]; zo[6 + j] = znew[j]; }
            float* so = g_s + ((size_t)k * B + b) * HLF;
#pragma unroll
            for (int j = 0; j < 6; j++) so[j] = sv[j];
            unsigned* m1o = g_m1 + ((size_t)k * B + b) * 6;
            unsigned* m2o = g_m2 + ((size_t)k * B + b) * 6;
#pragma unroll
            for (int i = 0; i < 6; i++) { m1o[i] = mm1[i]; m2o[i] = mm2[i]; }
            g_ld[b] -= ssum;
        }
    }
}

// ---------------- log_prob folded into kl kernel (needs only stage 1) --------

// ---------------- VJP layer: V <- J_fk(z_k)^T V ----------------
__global__ void __launch_bounds__(256) k_vjp_layer(
    const float* __restrict__ W1, const float* __restrict__ W2,
    const float* __restrict__ W3, int k)
{
    extern __shared__ float sm[];
    float* W1s = sm;                    // [192][6] row-major
    float* W2s = W1s + HID * HLF;       // [192][192] row-major
    float* W3s = W2s + HID * HID;       // [12][192] row-major
    float* gh2 = W3s + 12 * HID;        // 8 warps * 6 * 192
    float* Vb  = gh2 + 8 * 6 * HID;     // 8 warps * 72

    int tid = threadIdx.x;
    for (int i = tid; i < HID * HLF; i += 256) W1s[i] = W1[i];
    for (int i = tid; i < HID * HID; i += 256) W2s[i] = W2[i];
    for (int i = tid; i < 12 * HID; i += 256)  W3s[i] = W3[i];
    __syncthreads();

    int lane = tid & 31, wip = tid >> 5;
    float* gh2w = gh2 + wip * 6 * HID;
    float* Vw   = Vb  + wip * 72;
    int w  = (blockIdx.x * 256 + tid) >> 5;
    int nw = gridDim.x * 8;

    for (int b = w; b < B; b += nw) {
        __syncwarp();
        for (int t = lane; t < 72; t += 32) Vw[t] = g_V[(size_t)b * 72 + t];
        __syncwarp();

        float es[6], fac[6];
        const float* sp = g_s  + ((size_t)k * B + b) * HLF;
        const float* zp = g_zk + ((size_t)k * B + b) * DIN;
#pragma unroll
        for (int j = 0; j < 6; j++) {
            float s = sp[j]; float e = expf(s); es[j] = e;
            float t2 = 0.5f * s;
            fac[j] = zp[6 + j] * e * (1.f - t2 * t2);  // d s / d sraw = 1 - tanh^2
        }
        unsigned m1v[6], m2v[6];
        const unsigned* m1p = g_m1 + ((size_t)k * B + b) * 6;
        const unsigned* m2p = g_m2 + ((size_t)k * B + b) * 6;
#pragma unroll
        for (int i = 0; i < 6; i++) { m1v[i] = m1p[i]; m2v[i] = m2p[i]; }

        // step 1: g_h2 = (g_prm @ W3) * mask2    (g_prm built on the fly)
        float acc[6][6];
#pragma unroll
        for (int v = 0; v < 6; v++)
#pragma unroll
            for (int kk = 0; kk < 6; kk++) acc[v][kk] = 0.f;
#pragma unroll
        for (int o = 0; o < 12; o++) {
            int j = o >> 1;
            float wv[6];
#pragma unroll
            for (int kk = 0; kk < 6; kk++) wv[kk] = W3s[o * HID + lane + 32 * kk];
#pragma unroll
            for (int v = 0; v < 6; v++) {
                float g = Vw[v * 12 + j];
                if (o & 1) g *= fac[j];
#pragma unroll
                for (int kk = 0; kk < 6; kk++) acc[v][kk] += g * wv[kk];
            }
        }
#pragma unroll
        for (int kk = 0; kk < 6; kk++) {
            float msk = ((m2v[kk] >> lane) & 1u) ? 1.f : 0.f;
#pragma unroll
            for (int v = 0; v < 6; v++) {
                acc[v][kk] *= msk;
                gh2w[v * HID + lane + 32 * kk] = acc[v][kk];
            }
        }
        __syncwarp();

        // step 2: g_h1 = (g_h2 @ W2) * mask1
        float a1[6][6];
#pragma unroll
        for (int v = 0; v < 6; v++)
#pragma unroll
            for (int kk = 0; kk < 6; kk++) a1[v][kk] = 0.f;
        for (int j = 0; j < HID; j++) {
            float wv[6];
#pragma unroll
            for (int kk = 0; kk < 6; kk++) wv[kk] = W2s[j * HID + lane + 32 * kk];
#pragma unroll
            for (int v = 0; v < 6; v++) {
                float g = gh2w[v * HID + j];
#pragma unroll
                for (int kk = 0; kk < 6; kk++) a1[v][kk] += g * wv[kk];
            }
        }
#pragma unroll
        for (int kk = 0; kk < 6; kk++) {
            float msk = ((m1v[kk] >> lane) & 1u) ? 1.f : 0.f;
#pragma unroll
            for (int v = 0; v < 6; v++) a1[v][kk] *= msk;
        }

        // step 3: g_z1 = g_h1 @ W1 (partial per lane, butterfly reduce)
        float pz[6][6];
#pragma unroll
        for (int v = 0; v < 6; v++)
#pragma unroll
            for (int j = 0; j < 6; j++) pz[v][j] = 0.f;
#pragma unroll
        for (int kk = 0; kk < 6; kk++) {
            int c = lane + 32 * kk;
            float w6[6];
#pragma unroll
            for (int j = 0; j < 6; j++) w6[j] = W1s[c * 6 + j];
#pragma unroll
            for (int v = 0; v < 6; v++)
#pragma unroll
                for (int j = 0; j < 6; j++) pz[v][j] += a1[v][kk] * w6[j];
        }
#pragma unroll
        for (int v = 0; v < 6; v++)
#pragma unroll
            for (int j = 0; j < 6; j++) {
                float x = pz[v][j];
#pragma unroll
                for (int off = 16; off > 0; off >>= 1) x += __shfl_xor_sync(0xffffffffu, x, off);
                pz[v][j] = x;
            }

        if (lane == 0) {
            float* vo = g_V + (size_t)b * 72;
#pragma unroll
            for (int v = 0; v < 6; v++)
#pragma unroll
                for (int j = 0; j < 6; j++) {
                    vo[v * 12 + j]     = Vw[v * 12 + 6 + j] + pz[v][j];   // wrt z1
                    vo[v * 12 + 6 + j] = Vw[v * 12 + j] * es[j];          // wrt z2
                }
        }
    }
}

// ---------------- deterministic Frobenius-norm reduction ----------------
__global__ void k_ssq_part() {
    float s = 0.f;
    for (int i = blockIdx.x * blockDim.x + threadIdx.x; i < B * 72; i += gridDim.x * blockDim.x) {
        float v = g_V[i]; s += v * v;
    }
    __shared__ float red[256];
    red[threadIdx.x] = s; __syncthreads();
    for (int o = 128; o > 0; o >>= 1) {
        if (threadIdx.x < o) red[threadIdx.x] += red[threadIdx.x + o];
        __syncthreads();
    }
    if (threadIdx.x == 0) g_part[blockIdx.x] = red[0];
}
__global__ void k_ssq_final() {
    __shared__ float red[256];
    red[threadIdx.x] = g_part[threadIdx.x]; __syncthreads();
    for (int o = 128; o > 0; o >>= 1) {
        if (threadIdx.x < o) red[threadIdx.x] += red[threadIdx.x + o];
        __syncthreads();
    }
    if (threadIdx.x == 0) g_ssq = red[0];
}

// ---------------- KL + log_prob (thread per sample) ----------------
__global__ void __launch_bounds__(128) k_kl(
    const float* __restrict__ Wsym, const float* __restrict__ lvd,
    float* __restrict__ out)
{
    __shared__ float As[NB * 144];  // A = Wsym - Wsym^T
    for (int i = threadIdx.x; i < NB * 144; i += blockDim.x) {
        int m = i / 144; int rc = i % 144; int r = rc / 12; int c = rc % 12;
        As[i] = Wsym[m * 144 + r * 12 + c] - Wsym[m * 144 + c * 12 + r];
    }
    __syncthreads();

    int b = blockIdx.x * blockDim.x + threadIdx.x;
    if (b >= B) return;

    float zr[12]; float zz = 0.f;
    for (int i = 0; i < 12; i++) { zr[i] = g_zk[(size_t)b * 12 + i]; zz += zr[i] * zr[i]; }
    out[b] = g_ld[b] - 6.f * 1.8378770664093453f - 0.5f * zz;  // log_prob

    float scale = rsqrtf(g_ssq);
    float Jp[6][12];
    for (int v = 0; v < 6; v++)
        for (int i = 0; i < 12; i++) Jp[v][i] = g_V[(size_t)b * 72 + v * 12 + i] * scale;

    float Sq[12][12];
    for (int n = 0; n < 12; n++) for (int m = 0; m < 12; m++) Sq[n][m] = 0.f;
    float trq = 0.f, trpq = 0.f;

    for (int m = 0; m < NB; m++) {
        const float* Am = As + m * 144;
        float Jq[12];
        for (int jj = 0; jj < 12; jj++) {
            float a = 0.f;
            for (int i = 0; i < 12; i++) a += zr[i] * Am[jj * 12 + i];
            Jq[jj] = a; trq += a * a;
        }
        for (int n = 0; n < 12; n++)
            for (int mm = 0; mm < 12; mm++) Sq[n][mm] += Jq[n] * Jq[mm];
        for (int v = 0; v < 6; v++) {
            float d = 0.f;
            for (int i = 0; i < 12; i++) d += Jp[v][i] * Jq[i];
            trpq += d * d;
        }
    }

    // M = S_p + eps*I, regularize
    float Mm[6][6];
    for (int a = 0; a < 6; a++)
        for (int c = 0; c < 6; c++) {
            float acc = 0.f;
            for (int i = 0; i < 12; i++) acc += Jp[a][i] * Jp[c][i];
            Mm[a][c] = acc;
        }
    for (int d = 0; d < 6; d++) Mm[d][d] += 1e-3f;
    float dm = 0.f;
    for (int d = 0; d < 6; d++) dm += Mm[d][d];
    float normM = fmaxf(dm * (1.f / 6.f), 1e-6f);
    for (int d = 0; d < 6; d++) Mm[d][d] += 1e-3f * normM;

    // H = S_q + diag(D), regularize
    float D[12];
    for (int i = 0; i < 12; i++) D[i] = expf(-lvd[i]);
    for (int d = 0; d < 12; d++) Sq[d][d] += D[d];
    float dh = 0.f;
    for (int d = 0; d < 12; d++) dh += Sq[d][d];
    float normH = fmaxf(dh * (1.f / 12.f), 1e-6f);
    for (int d = 0; d < 12; d++) Sq[d][d] += 1e-3f * normH;

    float Db[12], sumDb = 0.f;
    for (int i = 0; i < 12; i++) { Db[i] = D[i] + 1e-3f * normH; sumDb += Db[i]; }

    float trp = 0.f;
    for (int v = 0; v < 6; v++)
        for (int i = 0; i < 12; i++) trp += Jp[v][i] * Jp[v][i] * Db[i];

    float trace = (1e-3f + 1e-3f * normM) * (sumDb + trq) + trp + trpq;

    // Cholesky 6x6 on Mm
    float ldM = 0.f;
    for (int c = 0; c < 6; c++) {
        float d = Mm[c][c];
        for (int kk = 0; kk < c; kk++) d -= Mm[c][kk] * Mm[c][kk];
        d = sqrtf(d); Mm[c][c] = d; ldM += 2.f * logf(d);
        float inv = 1.f / d;
        for (int r = c + 1; r < 6; r++) {
            float a = Mm[r][c];
            for (int kk = 0; kk < c; kk++) a -= Mm[r][kk] * Mm[c][kk];
            Mm[r][c] = a * inv;
        }
    }
    // Cholesky 12x12 on Sq (=H)
    float ldH = 0.f;
    for (int c = 0; c < 12; c++) {
        float d = Sq[c][c];
        for (int kk = 0; kk < c; kk++) d -= Sq[c][kk] * Sq[c][kk];
        d = sqrtf(d); Sq[c][c] = d; ldH += 2.f * logf(d);
        float inv = 1.f / d;
        for (int r = c + 1; r < 12; r++) {
            float a = Sq[r][c];
            for (int kk = 0; kk < c; kk++) a -= Sq[r][kk] * Sq[c][kk];
            Sq[r][c] = a * inv;
        }
    }

    float logdet_p = ldM + 6.f * (-6.907755278982137f);  // (in-out)*log(eps_p)
    out[B + b] = 0.5f * (trace - logdet_p - ldH - 12.f);
}

// ---------------- host launcher ----------------
extern "C" void kernel_launch(void* const* d_in, const int* in_sizes, int n_in,
                              void* d_out, int out_size) {
    const float* y    = (const float*)d_in[0];
    const float* Jp   = (const float*)d_in[1];
    const float* W1   = (const float*)d_in[2];
    const float* b1   = (const float*)d_in[3];
    const float* W2   = (const float*)d_in[4];
    const float* b2   = (const float*)d_in[5];
    const float* W3   = (const float*)d_in[6];
    const float* b3   = (const float*)d_in[7];
    const float* Wsym = (const float*)d_in[8];
    const float* lvd  = (const float*)d_in[9];
    float* out = (float*)d_out;

    const int SMEM_INV = (HLF * HID + HID + HID * 193 + HID + 12 * HID + 16 + 8 * HID) * 4;
    const int SMEM_VJP = (HID * HLF + HID * HID + 12 * HID + 8 * 6 * HID + 8 * 72) * 4;
    cudaFuncSetAttribute(k_inv_layer, cudaFuncAttributeMaxDynamicSharedMemorySize, SMEM_INV);
    cudaFuncSetAttribute(k_vjp_layer, cudaFuncAttributeMaxDynamicSharedMemorySize, SMEM_VJP);

    k_init<<<256, 256>>>(y, Jp);

    for (int k = LAYERS - 1; k >= 0; k--) {
        k_inv_layer<<<152, 256, SMEM_INV>>>(
            W1 + (size_t)k * HID * HLF, b1 + (size_t)k * HID,
            W2 + (size_t)k * HID * HID, b2 + (size_t)k * HID,
            W3 + (size_t)k * 12 * HID,  b3 + (size_t)k * 12, k);
    }
    for (int k = LAYERS - 1; k >= 0; k--) {
        k_vjp_layer<<<152, 256, SMEM_VJP>>>(
            W1 + (size_t)k * HID * HLF,
            W2 + (size_t)k * HID * HID,
            W3 + (size_t)k * 12 * HID, k);
    }
    k_ssq_part<<<256, 256>>>();
    k_ssq_final<<<1, 256>>>();
    k_kl<<<(B + 127) / 128, 128>>>(Wsym, lvd, out);
}

// round 2
// speedup vs baseline: 1.5363x; 1.5363x over previous
#include <cuda_runtime.h>
#include <math.h>

#define B     16384
#define DIN   12
#define HLF   6
#define HID   192
#define LAYERS 24
#define NB    66

// ---------------- scratch (static device globals; no allocs) ----------------
__device__ float    g_zk[(LAYERS + 1) * B * DIN];   // z_k, k=0..24 (24 = y)
__device__ float    g_s [LAYERS * B * HLF];         // per-layer s
__device__ unsigned g_m1[LAYERS * B * 6];           // relu masks layer 1
__device__ unsigned g_m2[LAYERS * B * 6];           // relu masks layer 2
__device__ float    g_V [B * 6 * DIN];              // cotangent state (6x12/sample)
__device__ float    g_ld[B];                        // log-det accumulator
__device__ float    g_part[256];
__device__ float    g_ssq;

// ---------------- init ----------------
__global__ void k_init(const float* __restrict__ y, const float* __restrict__ Jp) {
    int i0 = blockIdx.x * blockDim.x + threadIdx.x;
    int st = gridDim.x * blockDim.x;
    for (int i = i0; i < B * 72; i += st) {
        g_V[i] = Jp[i];
        if (i < B * DIN) g_zk[LAYERS * B * DIN + i] = y[i];
        if (i < B)       g_ld[i] = 0.f;
    }
}

// ---------------- inverse coupling layer (sparse j-loop via compaction) -----
__global__ void __launch_bounds__(512) k_inv_layer(
    const float* __restrict__ W1, const float* __restrict__ b1,
    const float* __restrict__ W2, const float* __restrict__ b2,
    const float* __restrict__ W3, const float* __restrict__ b3, int k)
{
    extern __shared__ float sm[];
    float*  W1t = sm;                 // [6][192] transposed
    float*  b1s = W1t + HLF * HID;    // 192
    float*  W2t = b1s + HID;          // [192][193] transposed+pad
    float*  b2s = W2t + HID * 193;    // 192
    float*  W3s = b2s + HID;          // [12][192]
    float*  b3s = W3s + 12 * HID;     // 16
    float2* prs = (float2*)(b3s + 16);// 16 warps * 192 pairs (h, idx)

    int tid = threadIdx.x;
    for (int i = tid; i < HLF * HID; i += 512) { int r = i / HLF, j = i % HLF; W1t[j * HID + r] = W1[i]; }
    for (int i = tid; i < HID; i += 512) { b1s[i] = b1[i]; b2s[i] = b2[i]; }
    for (int i = tid; i < HID * HID; i += 512) { int r = i / HID, j = i % HID; W2t[j * 193 + r] = W2[i]; }
    for (int i = tid; i < 12 * HID; i += 512) W3s[i] = W3[i];
    if (tid < 12) b3s[tid] = b3[tid];
    __syncthreads();

    int lane = tid & 31, wip = tid >> 5;
    float2* pw = prs + wip * HID;
    unsigned lt = (1u << lane) - 1u;
    int w  = (blockIdx.x * 512 + tid) >> 5;
    int nw = gridDim.x * 16;

    for (int b = w; b < B; b += nw) {
        __syncwarp();
        const float* zin = g_zk + ((size_t)(k + 1) * B + b) * DIN;
        float z1[6], z2[6];
#pragma unroll
        for (int j = 0; j < 6; j++) { z1[j] = zin[6 + j]; z2[j] = zin[j]; }

        // layer 1 + compaction of active h1
        unsigned mm1[6];
        int base = 0;
#pragma unroll
        for (int i = 0; i < 6; i++) {
            int r = lane + 32 * i;
            float a = b1s[r];
#pragma unroll
            for (int j = 0; j < 6; j++) a = fmaf(W1t[j * HID + r], z1[j], a);
            unsigned m = __ballot_sync(0xffffffffu, a > 0.f);
            mm1[i] = m;
            if (m & (1u << lane)) {
                int pos = base + __popc(m & lt);
                pw[pos] = make_float2(a, __int_as_float(r));
            }
            base += __popc(m);
        }
        int cnt = base;
        __syncwarp();

        // layer 2: sparse j loop
        float h2a[6];
#pragma unroll
        for (int i = 0; i < 6; i++) h2a[i] = b2s[lane + 32 * i];
        int c = 0;
        for (; c + 2 <= cnt; c += 2) {
            float2 p0 = pw[c], p1 = pw[c + 1];
            const float* w0 = W2t + __float_as_int(p0.y) * 193 + lane;
            const float* w1 = W2t + __float_as_int(p1.y) * 193 + lane;
#pragma unroll
            for (int i = 0; i < 6; i++)
                h2a[i] = fmaf(w1[32 * i], p1.x, fmaf(w0[32 * i], p0.x, h2a[i]));
        }
        if (c < cnt) {
            float2 p0 = pw[c];
            const float* w0 = W2t + __float_as_int(p0.y) * 193 + lane;
#pragma unroll
            for (int i = 0; i < 6; i++) h2a[i] = fmaf(w0[32 * i], p0.x, h2a[i]);
        }
        unsigned mm2[6];
#pragma unroll
        for (int i = 0; i < 6; i++) {
            mm2[i] = __ballot_sync(0xffffffffu, h2a[i] > 0.f);
            h2a[i] = fmaxf(h2a[i], 0.f);
        }

        // layer 3 (dense, small) + warp reduce
        float pp[12];
#pragma unroll
        for (int o = 0; o < 12; o++) {
            float a = 0.f;
#pragma unroll
            for (int i = 0; i < 6; i++) a = fmaf(W3s[o * HID + lane + 32 * i], h2a[i], a);
#pragma unroll
            for (int off = 16; off > 0; off >>= 1) a += __shfl_xor_sync(0xffffffffu, a, off);
            pp[o] = a;
        }

        float ssum = 0.f, sv[6], znew[6];
#pragma unroll
        for (int j = 0; j < 6; j++) {
            float sh = pp[2 * j] + b3s[2 * j];
            float sr = pp[2 * j + 1] + b3s[2 * j + 1];
            float s  = 2.f * tanhf(0.5f * sr);
            sv[j] = s; ssum += s;
            znew[j] = (z2[j] - sh) * expf(-s);
        }
        if (lane == 0) {
            float* zo = g_zk + ((size_t)k * B + b) * DIN;
#pragma unroll
            for (int j = 0; j < 6; j++) { zo[j] = z1[j]; zo[6 + j] = znew[j]; }
            float* so = g_s + ((size_t)k * B + b) * HLF;
#pragma unroll
            for (int j = 0; j < 6; j++) so[j] = sv[j];
            unsigned* m1o = g_m1 + ((size_t)k * B + b) * 6;
            unsigned* m2o = g_m2 + ((size_t)k * B + b) * 6;
#pragma unroll
            for (int i = 0; i < 6; i++) { m1o[i] = mm1[i]; m2o[i] = mm2[i]; }
            g_ld[b] -= ssum;
        }
    }
}

// ---------------- VJP layer: V <- J_fk(z_k)^T V  (sparse step 2) ------------
__global__ void __launch_bounds__(256, 1) k_vjp_layer(
    const float* __restrict__ W1, const float* __restrict__ W2,
    const float* __restrict__ W3, int k)
{
    extern __shared__ float sm[];
    float* W1s = sm;                    // [192][6]
    float* W2s = W1s + HID * HLF;       // [192][192] row-major
    float* W3s = W2s + HID * HID;       // [12][192]
    float* gq  = W3s + 12 * HID;        // 8 warps * 192 * 8 floats (idx + 6 vals + pad)
    float* Vb  = gq + 8 * HID * 8;      // 8 warps * 72

    int tid = threadIdx.x;
    for (int i = tid; i < HID * HLF; i += 256) W1s[i] = W1[i];
    for (int i = tid; i < HID * HID; i += 256) W2s[i] = W2[i];
    for (int i = tid; i < 12 * HID; i += 256)  W3s[i] = W3[i];
    __syncthreads();

    int lane = tid & 31, wip = tid >> 5;
    float* gw = gq + wip * HID * 8;
    float* Vw = Vb + wip * 72;
    unsigned lt = (1u << lane) - 1u;
    int w  = (blockIdx.x * 256 + tid) >> 5;
    int nw = gridDim.x * 8;

    for (int b = w; b < B; b += nw) {
        __syncwarp();
        for (int t = lane; t < 72; t += 32) Vw[t] = g_V[(size_t)b * 72 + t];
        __syncwarp();

        float es[6], fac[6];
        const float* sp = g_s  + ((size_t)k * B + b) * HLF;
        const float* zp = g_zk + ((size_t)k * B + b) * DIN;
#pragma unroll
        for (int j = 0; j < 6; j++) {
            float s = sp[j]; float e = expf(s); es[j] = e;
            float t2 = 0.5f * s;
            fac[j] = zp[6 + j] * e * (1.f - t2 * t2);
        }
        unsigned m1v[6], m2v[6];
        const unsigned* m1p = g_m1 + ((size_t)k * B + b) * 6;
        const unsigned* m2p = g_m2 + ((size_t)k * B + b) * 6;
#pragma unroll
        for (int i = 0; i < 6; i++) { m1v[i] = m1p[i]; m2v[i] = m2p[i]; }

        // step 1: acc[v][kk] = (g_prm @ W3) at j = lane+32kk
        float acc[6][6];
#pragma unroll
        for (int v = 0; v < 6; v++)
#pragma unroll
            for (int kk = 0; kk < 6; kk++) acc[v][kk] = 0.f;
#pragma unroll
        for (int o = 0; o < 12; o++) {
            int j = o >> 1;
            float wv[6];
#pragma unroll
            for (int kk = 0; kk < 6; kk++) wv[kk] = W3s[o * HID + lane + 32 * kk];
#pragma unroll
            for (int v = 0; v < 6; v++) {
                float g = Vw[v * 12 + j];
                if (o & 1) g *= fac[j];
#pragma unroll
                for (int kk = 0; kk < 6; kk++) acc[v][kk] = fmaf(g, wv[kk], acc[v][kk]);
            }
        }

        // compact active (mask2) columns of g_h2 into gw
        int base = 0;
#pragma unroll
        for (int kk = 0; kk < 6; kk++) {
            unsigned m = m2v[kk];
            if (m & (1u << lane)) {
                int pos = base + __popc(m & lt);
                float4* q = (float4*)(gw + pos * 8);
                q[0] = make_float4(__int_as_float(lane + 32 * kk), acc[0][kk], acc[1][kk], acc[2][kk]);
                q[1] = make_float4(acc[3][kk], acc[4][kk], acc[5][kk], 0.f);
            }
            base += __popc(m);
        }
        int cnt = base;
        __syncwarp();

        // step 2: a1[v][kk] = sum over active j of g[v][j] * W2[j][lane+32kk]
        float a1[6][6];
#pragma unroll
        for (int v = 0; v < 6; v++)
#pragma unroll
            for (int kk = 0; kk < 6; kk++) a1[v][kk] = 0.f;
        for (int c = 0; c < cnt; c++) {
            const float4* q = (const float4*)(gw + c * 8);
            float4 q0 = q[0], q1 = q[1];
            int j = __float_as_int(q0.x);
            const float* wp = W2s + j * HID + lane;
#pragma unroll
            for (int kk = 0; kk < 6; kk++) {
                float wv = wp[32 * kk];
                a1[0][kk] = fmaf(q0.y, wv, a1[0][kk]);
                a1[1][kk] = fmaf(q0.z, wv, a1[1][kk]);
                a1[2][kk] = fmaf(q0.w, wv, a1[2][kk]);
                a1[3][kk] = fmaf(q1.x, wv, a1[3][kk]);
                a1[4][kk] = fmaf(q1.y, wv, a1[4][kk]);
                a1[5][kk] = fmaf(q1.z, wv, a1[5][kk]);
            }
        }
#pragma unroll
        for (int kk = 0; kk < 6; kk++) {
            float msk = ((m1v[kk] >> lane) & 1u) ? 1.f : 0.f;
#pragma unroll
            for (int v = 0; v < 6; v++) a1[v][kk] *= msk;
        }

        // step 3: g_z1 = g_h1 @ W1, butterfly reduce
        float pz[6][6];
#pragma unroll
        for (int v = 0; v < 6; v++)
#pragma unroll
            for (int j = 0; j < 6; j++) pz[v][j] = 0.f;
#pragma unroll
        for (int kk = 0; kk < 6; kk++) {
            int cc = lane + 32 * kk;
            float w6[6];
#pragma unroll
            for (int j = 0; j < 6; j++) w6[j] = W1s[cc * 6 + j];
#pragma unroll
            for (int v = 0; v < 6; v++)
#pragma unroll
                for (int j = 0; j < 6; j++) pz[v][j] = fmaf(a1[v][kk], w6[j], pz[v][j]);
        }
#pragma unroll
        for (int v = 0; v < 6; v++)
#pragma unroll
            for (int j = 0; j < 6; j++) {
                float x = pz[v][j];
#pragma unroll
                for (int off = 16; off > 0; off >>= 1) x += __shfl_xor_sync(0xffffffffu, x, off);
                pz[v][j] = x;
            }

        if (lane == 0) {
            float* vo = g_V + (size_t)b * 72;
#pragma unroll
            for (int v = 0; v < 6; v++)
#pragma unroll
                for (int j = 0; j < 6; j++) {
                    vo[v * 12 + j]     = Vw[v * 12 + 6 + j] + pz[v][j];
                    vo[v * 12 + 6 + j] = Vw[v * 12 + j] * es[j];
                }
        }
    }
}

// ---------------- deterministic Frobenius-norm reduction ----------------
__global__ void k_ssq_part() {
    float s = 0.f;
    for (int i = blockIdx.x * blockDim.x + threadIdx.x; i < B * 72; i += gridDim.x * blockDim.x) {
        float v = g_V[i]; s += v * v;
    }
    __shared__ float red[256];
    red[threadIdx.x] = s; __syncthreads();
    for (int o = 128; o > 0; o >>= 1) {
        if (threadIdx.x < o) red[threadIdx.x] += red[threadIdx.x + o];
        __syncthreads();
    }
    if (threadIdx.x == 0) g_part[blockIdx.x] = red[0];
}
__global__ void k_ssq_final() {
    __shared__ float red[256];
    red[threadIdx.x] = g_part[threadIdx.x]; __syncthreads();
    for (int o = 128; o > 0; o >>= 1) {
        if (threadIdx.x < o) red[threadIdx.x] += red[threadIdx.x + o];
        __syncthreads();
    }
    if (threadIdx.x == 0) g_ssq = red[0];
}

// ---------------- KL + log_prob (thread per sample, packed triangular) ------
#define LIX(r, c) ((r) * ((r) + 1) / 2 + (c))

__global__ void __launch_bounds__(64) k_kl(
    const float* __restrict__ Wsym, const float* __restrict__ lvd,
    float* __restrict__ out)
{
    __shared__ float As[NB * 144];
    for (int i = threadIdx.x; i < NB * 144; i += 64) {
        int m = i / 144; int rc = i % 144; int r = rc / 12; int c = rc % 12;
        As[i] = Wsym[m * 144 + r * 12 + c] - Wsym[m * 144 + c * 12 + r];
    }
    __syncthreads();

    int b = blockIdx.x * 64 + threadIdx.x;
    if (b >= B) return;

    float zr[12]; float zz = 0.f;
#pragma unroll
    for (int i = 0; i < 12; i++) { zr[i] = g_zk[(size_t)b * 12 + i]; zz += zr[i] * zr[i]; }
    out[b] = g_ld[b] - 6.f * 1.8378770664093453f - 0.5f * zz;

    float scale = rsqrtf(g_ssq);
    float Jp[6][12];
#pragma unroll
    for (int v = 0; v < 6; v++)
#pragma unroll
        for (int i = 0; i < 12; i++) Jp[v][i] = g_V[(size_t)b * 72 + v * 12 + i] * scale;

    float Sql[78];
#pragma unroll
    for (int i = 0; i < 78; i++) Sql[i] = 0.f;
    float trq = 0.f, trpq = 0.f;

    for (int m = 0; m < NB; m++) {
        const float* Am = As + m * 144;
        float Jq[12];
#pragma unroll
        for (int jj = 0; jj < 12; jj++) {
            float a = 0.f;
#pragma unroll
            for (int i = 0; i < 12; i++) a = fmaf(zr[i], Am[jj * 12 + i], a);
            Jq[jj] = a; trq = fmaf(a, a, trq);
        }
#pragma unroll
        for (int n = 0; n < 12; n++)
#pragma unroll
            for (int mm = 0; mm <= n; mm++) Sql[LIX(n, mm)] = fmaf(Jq[n], Jq[mm], Sql[LIX(n, mm)]);
#pragma unroll
        for (int v = 0; v < 6; v++) {
            float d = 0.f;
#pragma unroll
            for (int i = 0; i < 12; i++) d = fmaf(Jp[v][i], Jq[i], d);
            trpq = fmaf(d, d, trpq);
        }
    }

    // M packed lower
    float Ml[21];
#pragma unroll
    for (int a = 0; a < 6; a++)
#pragma unroll
        for (int c = 0; c <= a; c++) {
            float acc = 0.f;
#pragma unroll
            for (int i = 0; i < 12; i++) acc = fmaf(Jp[a][i], Jp[c][i], acc);
            Ml[LIX(a, c)] = acc;
        }
#pragma unroll
    for (int d = 0; d < 6; d++) Ml[LIX(d, d)] += 1e-3f;
    float dm = 0.f;
#pragma unroll
    for (int d = 0; d < 6; d++) dm += Ml[LIX(d, d)];
    float normM = fmaxf(dm * (1.f / 6.f), 1e-6f);
#pragma unroll
    for (int d = 0; d < 6; d++) Ml[LIX(d, d)] += 1e-3f * normM;

    // H packed lower
    float D[12];
#pragma unroll
    for (int i = 0; i < 12; i++) D[i] = expf(-lvd[i]);
#pragma unroll
    for (int d = 0; d < 12; d++) Sql[LIX(d, d)] += D[d];
    float dh = 0.f;
#pragma unroll
    for (int d = 0; d < 12; d++) dh += Sql[LIX(d, d)];
    float normH = fmaxf(dh * (1.f / 12.f), 1e-6f);
#pragma unroll
    for (int d = 0; d < 12; d++) Sql[LIX(d, d)] += 1e-3f * normH;

    float Db[12], sumDb = 0.f;
#pragma unroll
    for (int i = 0; i < 12; i++) { Db[i] = D[i] + 1e-3f * normH; sumDb += Db[i]; }

    float trp = 0.f;
#pragma unroll
    for (int v = 0; v < 6; v++)
#pragma unroll
        for (int i = 0; i < 12; i++) trp = fmaf(Jp[v][i] * Jp[v][i], Db[i], trp);

    float trace = (1e-3f + 1e-3f * normM) * (sumDb + trq) + trp + trpq;

    // Cholesky 6x6 packed
    float ldM = 0.f;
#pragma unroll
    for (int c = 0; c < 6; c++) {
        float d = Ml[LIX(c, c)];
#pragma unroll
        for (int kk = 0; kk < c; kk++) d -= Ml[LIX(c, kk)] * Ml[LIX(c, kk)];
        d = sqrtf(d); ldM += 2.f * logf(d);
        float inv = 1.f / d;
#pragma unroll
        for (int r = c + 1; r < 6; r++) {
            float a = Ml[LIX(r, c)];
#pragma unroll
            for (int kk = 0; kk < c; kk++) a -= Ml[LIX(r, kk)] * Ml[LIX(c, kk)];
            Ml[LIX(r, c)] = a * inv;
        }
    }
    // Cholesky 12x12 packed
    float ldH = 0.f;
#pragma unroll
    for (int c = 0; c < 12; c++) {
        float d = Sql[LIX(c, c)];
#pragma unroll
        for (int kk = 0; kk < c; kk++) d -= Sql[LIX(c, kk)] * Sql[LIX(c, kk)];
        d = sqrtf(d); ldH += 2.f * logf(d);
        float inv = 1.f / d;
#pragma unroll
        for (int r = c + 1; r < 12; r++) {
            float a = Sql[LIX(r, c)];
#pragma unroll
            for (int kk = 0; kk < c; kk++) a -= Sql[LIX(r, kk)] * Sql[LIX(c, kk)];
            Sql[LIX(r, c)] = a * inv;
        }
    }

    float logdet_p = ldM + 6.f * (-6.907755278982137f);
    out[B + b] = 0.5f * (trace - logdet_p - ldH - 12.f);
}

// ---------------- host launcher ----------------
extern "C" void kernel_launch(void* const* d_in, const int* in_sizes, int n_in,
                              void* d_out, int out_size) {
    const float* y    = (const float*)d_in[0];
    const float* Jp   = (const float*)d_in[1];
    const float* W1   = (const float*)d_in[2];
    const float* b1   = (const float*)d_in[3];
    const float* W2   = (const float*)d_in[4];
    const float* b2   = (const float*)d_in[5];
    const float* W3   = (const float*)d_in[6];
    const float* b3   = (const float*)d_in[7];
    const float* Wsym = (const float*)d_in[8];
    const float* lvd  = (const float*)d_in[9];
    float* out = (float*)d_out;

    const int SMEM_INV = (HLF * HID + HID + HID * 193 + HID + 12 * HID + 16) * 4 + 16 * HID * 8;
    const int SMEM_VJP = (HID * HLF + HID * HID + 12 * HID + 8 * HID * 8 + 8 * 72) * 4;
    cudaFuncSetAttribute(k_inv_layer, cudaFuncAttributeMaxDynamicSharedMemorySize, SMEM_INV);
    cudaFuncSetAttribute(k_vjp_layer, cudaFuncAttributeMaxDynamicSharedMemorySize, SMEM_VJP);

    k_init<<<256, 256>>>(y, Jp);

    for (int k = LAYERS - 1; k >= 0; k--) {
        k_inv_layer<<<152, 512, SMEM_INV>>>(
            W1 + (size_t)k * HID * HLF, b1 + (size_t)k * HID,
            W2 + (size_t)k * HID * HID, b2 + (size_t)k * HID,
            W3 + (size_t)k * 12 * HID,  b3 + (size_t)k * 12, k);
    }
    for (int k = LAYERS - 1; k >= 0; k--) {
        k_vjp_layer<<<152, 256, SMEM_VJP>>>(
            W1 + (size_t)k * HID * HLF,
            W2 + (size_t)k * HID * HID,
            W3 + (size_t)k * 12 * HID, k);
    }
    k_ssq_part<<<256, 256>>>();
    k_ssq_final<<<1, 256>>>();
    k_kl<<<(B + 63) / 64, 64>>>(Wsym, lvd, out);
}

// round 3
// speedup vs baseline: 1.5832x; 1.0305x over previous
#include <cuda_runtime.h>
#include <math.h>

#define B     16384
#define DIN   12
#define HLF   6
#define HID   192
#define LAYERS 24
#define NB    66

// ---------------- scratch (static device globals; no allocs) ----------------
__device__ float    g_zk[(LAYERS + 1) * B * DIN];
__device__ float    g_s [LAYERS * B * HLF];
__device__ unsigned g_m1[LAYERS * B * 6];
__device__ unsigned g_m2[LAYERS * B * 6];
__device__ float    g_V [B * 6 * DIN];
__device__ float    g_ld[B];
__device__ float    g_part[256];
__device__ float    g_ssq;

// ---------------- init ----------------
__global__ void k_init(const float* __restrict__ y, const float* __restrict__ Jp) {
    int i0 = blockIdx.x * blockDim.x + threadIdx.x;
    int st = gridDim.x * blockDim.x;
    for (int i = i0; i < B * 72; i += st) {
        g_V[i] = Jp[i];
        if (i < B * DIN) g_zk[LAYERS * B * DIN + i] = y[i];
        if (i < B)       g_ld[i] = 0.f;
    }
}

// pick a[0..5] by index i (register-array safe select chain)
__device__ __forceinline__ float pick6(const float a[6], int i) {
    float r = a[0];
    if (i == 1) r = a[1];
    if (i == 2) r = a[2];
    if (i == 3) r = a[3];
    if (i == 4) r = a[4];
    if (i == 5) r = a[5];
    return r;
}
__device__ __forceinline__ unsigned pick6u(const unsigned a[6], int i) {
    unsigned r = a[0];
    if (i == 1) r = a[1];
    if (i == 2) r = a[2];
    if (i == 3) r = a[3];
    if (i == 4) r = a[4];
    if (i == 5) r = a[5];
    return r;
}

// ---------------- inverse coupling layer ----------------
__global__ void __launch_bounds__(512) k_inv_layer(
    const float* __restrict__ W1, const float* __restrict__ b1,
    const float* __restrict__ W2, const float* __restrict__ b2,
    const float* __restrict__ W3, const float* __restrict__ b3, int k)
{
    extern __shared__ float sm[];
    float*  W1t = sm;                 // [6][192]
    float*  b1s = W1t + HLF * HID;
    float*  W2t = b1s + HID;          // [192][193] transposed+pad
    float*  b2s = W2t + HID * 193;
    float*  W3s = b2s + HID;          // [12][192]
    float*  b3s = W3s + 12 * HID;
    float2* prs = (float2*)(b3s + 16);// 16 warps * 192

    int tid = threadIdx.x;
    for (int i = tid; i < HLF * HID; i += 512) { int r = i / HLF, j = i % HLF; W1t[j * HID + r] = W1[i]; }
    for (int i = tid; i < HID; i += 512) { b1s[i] = b1[i]; b2s[i] = b2[i]; }
    for (int i = tid; i < HID * HID; i += 512) { int r = i / HID, j = i % HID; W2t[j * 193 + r] = W2[i]; }
    for (int i = tid; i < 12 * HID; i += 512) W3s[i] = W3[i];
    if (tid < 12) b3s[tid] = b3[tid];
    __syncthreads();

    int lane = tid & 31, wip = tid >> 5;
    float2* pw = prs + wip * HID;
    unsigned lt = (1u << lane) - 1u;
    int w  = (blockIdx.x * 512 + tid) >> 5;
    int nw = gridDim.x * 16;

    for (int b = w; b < B; b += nw) {
        __syncwarp();
        const float* zin = g_zk + ((size_t)(k + 1) * B + b) * DIN;
        float z1[6], z2[6];
#pragma unroll
        for (int j = 0; j < 6; j++) { z1[j] = zin[6 + j]; z2[j] = zin[j]; }

        unsigned mm1[6];
        int base = 0;
#pragma unroll
        for (int i = 0; i < 6; i++) {
            int r = lane + 32 * i;
            float a = b1s[r];
#pragma unroll
            for (int j = 0; j < 6; j++) a = fmaf(W1t[j * HID + r], z1[j], a);
            unsigned m = __ballot_sync(0xffffffffu, a > 0.f);
            mm1[i] = m;
            if (m & (1u << lane)) {
                int pos = base + __popc(m & lt);
                pw[pos] = make_float2(a, __int_as_float(r));
            }
            base += __popc(m);
        }
        int cnt = base;
        __syncwarp();

        float h2a[6];
#pragma unroll
        for (int i = 0; i < 6; i++) h2a[i] = b2s[lane + 32 * i];
        int c = 0;
        for (; c + 2 <= cnt; c += 2) {
            float2 p0 = pw[c], p1 = pw[c + 1];
            const float* w0 = W2t + __float_as_int(p0.y) * 193 + lane;
            const float* w1 = W2t + __float_as_int(p1.y) * 193 + lane;
#pragma unroll
            for (int i = 0; i < 6; i++)
                h2a[i] = fmaf(w1[32 * i], p1.x, fmaf(w0[32 * i], p0.x, h2a[i]));
        }
        if (c < cnt) {
            float2 p0 = pw[c];
            const float* w0 = W2t + __float_as_int(p0.y) * 193 + lane;
#pragma unroll
            for (int i = 0; i < 6; i++) h2a[i] = fmaf(w0[32 * i], p0.x, h2a[i]);
        }
        unsigned mm2[6];
#pragma unroll
        for (int i = 0; i < 6; i++) {
            mm2[i] = __ballot_sync(0xffffffffu, h2a[i] > 0.f);
            h2a[i] = fmaxf(h2a[i], 0.f);
        }

        float pp[12];
#pragma unroll
        for (int o = 0; o < 12; o++) {
            float a = 0.f;
#pragma unroll
            for (int i = 0; i < 6; i++) a = fmaf(W3s[o * HID + lane + 32 * i], h2a[i], a);
#pragma unroll
            for (int off = 16; off > 0; off >>= 1) a += __shfl_xor_sync(0xffffffffu, a, off);
            pp[o] = a;
        }

        float ssum = 0.f, sv[6], znew[6];
#pragma unroll
        for (int j = 0; j < 6; j++) {
            float sh = pp[2 * j] + b3s[2 * j];
            float sr = pp[2 * j + 1] + b3s[2 * j + 1];
            float s  = 2.f * tanhf(0.5f * sr);
            sv[j] = s; ssum += s;
            znew[j] = (z2[j] - sh) * expf(-s);
        }
        // parallel epilogue stores (all lanes hold all values)
        {
            float* zo = g_zk + ((size_t)k * B + b) * DIN;
            if (lane < 12) {
                float v = (lane < 6) ? pick6(z1, lane) : pick6(znew, lane - 6);
                zo[lane] = v;
            }
            float* so = g_s + ((size_t)k * B + b) * HLF;
            if (lane >= 16 && lane < 22) so[lane - 16] = pick6(sv, lane - 16);
            unsigned* m1o = g_m1 + ((size_t)k * B + b) * 6;
            unsigned* m2o = g_m2 + ((size_t)k * B + b) * 6;
            if (lane >= 24 && lane < 30) m1o[lane - 24] = pick6u(mm1, lane - 24);
            if (lane >= 8 && lane < 14)  m2o[lane - 8]  = pick6u(mm2, lane - 8);
            if (lane == 31) g_ld[b] -= ssum;
        }
    }
}

// ---------------- VJP layer: dual-sided sparsity ----------------
__global__ void __launch_bounds__(256, 1) k_vjp_layer(
    const float* __restrict__ W1, const float* __restrict__ W2,
    const float* __restrict__ W3, int k)
{
    extern __shared__ float sm[];
    float* W1s = sm;                    // [192][6]
    float* W2s = W1s + HID * HLF;       // [192][192] row-major
    float* W3s = W2s + HID * HID;       // [12][192]
    float* gq  = W3s + 12 * HID;        // 8 warps * 192 * 8 (idx + 6 g-vals + pad)
    int*   c1q = (int*)(gq + 8 * HID * 8); // 8 warps * 192 active-col lists
    float* Vb  = (float*)(c1q + 8 * HID);  // 8 warps * 72

    int tid = threadIdx.x;
    for (int i = tid; i < HID * HLF; i += 256) W1s[i] = W1[i];
    for (int i = tid; i < HID * HID; i += 256) W2s[i] = W2[i];
    for (int i = tid; i < 12 * HID; i += 256)  W3s[i] = W3[i];
    __syncthreads();

    int lane = tid & 31, wip = tid >> 5;
    float* gw  = gq + wip * HID * 8;
    int*   c1w = c1q + wip * HID;
    float* Vw  = Vb + wip * 72;
    unsigned lt = (1u << lane) - 1u;
    int w  = (blockIdx.x * 256 + tid) >> 5;
    int nw = gridDim.x * 8;

    for (int b = w; b < B; b += nw) {
        __syncwarp();
        for (int t = lane; t < 72; t += 32) Vw[t] = g_V[(size_t)b * 72 + t];

        float es[6], fac[6];
        const float* sp = g_s  + ((size_t)k * B + b) * HLF;
        const float* zp = g_zk + ((size_t)k * B + b) * DIN;
#pragma unroll
        for (int j = 0; j < 6; j++) {
            float s = sp[j]; float e = expf(s); es[j] = e;
            float t2 = 0.5f * s;
            fac[j] = zp[6 + j] * e * (1.f - t2 * t2);
        }
        unsigned m1v[6], m2v[6];
        const unsigned* m1p = g_m1 + ((size_t)k * B + b) * 6;
        const unsigned* m2p = g_m2 + ((size_t)k * B + b) * 6;
#pragma unroll
        for (int i = 0; i < 6; i++) { m1v[i] = m1p[i]; m2v[i] = m2p[i]; }

        // build m1-active column list
        int base1 = 0;
#pragma unroll
        for (int i = 0; i < 6; i++) {
            unsigned m = m1v[i];
            if (m & (1u << lane)) c1w[base1 + __popc(m & lt)] = lane + 32 * i;
            base1 += __popc(m);
        }
        int cnt1 = base1;

        // step 1: acc[v][kk] = (g_prm @ W3) at j = lane+32kk
        float acc[6][6];
#pragma unroll
        for (int v = 0; v < 6; v++)
#pragma unroll
            for (int kk = 0; kk < 6; kk++) acc[v][kk] = 0.f;
#pragma unroll
        for (int o = 0; o < 12; o++) {
            int j = o >> 1;
            float wv[6];
#pragma unroll
            for (int kk = 0; kk < 6; kk++) wv[kk] = W3s[o * HID + lane + 32 * kk];
#pragma unroll
            for (int v = 0; v < 6; v++) {
                float g = Vw[v * 12 + j];
                if (o & 1) g *= fac[j];
#pragma unroll
                for (int kk = 0; kk < 6; kk++) acc[v][kk] = fmaf(g, wv[kk], acc[v][kk]);
            }
        }

        // compact m2-active rows of g_h2 into gw
        int base2 = 0;
#pragma unroll
        for (int kk = 0; kk < 6; kk++) {
            unsigned m = m2v[kk];
            if (m & (1u << lane)) {
                int pos = base2 + __popc(m & lt);
                float4* q = (float4*)(gw + pos * 8);
                q[0] = make_float4(__int_as_float(lane + 32 * kk), acc[0][kk], acc[1][kk], acc[2][kk]);
                q[1] = make_float4(acc[3][kk], acc[4][kk], acc[5][kk], 0.f);
            }
            base2 += __popc(m);
        }
        int cnt2 = base2;
        __syncwarp();

        float pz[6][6];
#pragma unroll
        for (int v = 0; v < 6; v++)
#pragma unroll
            for (int j = 0; j < 6; j++) pz[v][j] = 0.f;

        // ---- main pass: compacted output columns p = lane + 32t, t<3 ----
        {
            int cmax = cnt1 < 96 ? cnt1 : 96;
            int cc[3]; float a1t[3][6];
#pragma unroll
            for (int t = 0; t < 3; t++) {
                int p = lane + 32 * t;
                cc[t] = (p < cmax) ? c1w[p] : 0;
#pragma unroll
                for (int v = 0; v < 6; v++) a1t[t][v] = 0.f;
            }
            for (int c = 0; c < cnt2; c++) {
                const float4* q = (const float4*)(gw + c * 8);
                float4 q0 = q[0], q1 = q[1];
                const float* wp = W2s + __float_as_int(q0.x) * HID;
                float w0 = wp[cc[0]], w1 = wp[cc[1]], w2 = wp[cc[2]];
                a1t[0][0] = fmaf(q0.y, w0, a1t[0][0]);
                a1t[0][1] = fmaf(q0.z, w0, a1t[0][1]);
                a1t[0][2] = fmaf(q0.w, w0, a1t[0][2]);
                a1t[0][3] = fmaf(q1.x, w0, a1t[0][3]);
                a1t[0][4] = fmaf(q1.y, w0, a1t[0][4]);
                a1t[0][5] = fmaf(q1.z, w0, a1t[0][5]);
                a1t[1][0] = fmaf(q0.y, w1, a1t[1][0]);
                a1t[1][1] = fmaf(q0.z, w1, a1t[1][1]);
                a1t[1][2] = fmaf(q0.w, w1, a1t[1][2]);
                a1t[1][3] = fmaf(q1.x, w1, a1t[1][3]);
                a1t[1][4] = fmaf(q1.y, w1, a1t[1][4]);
                a1t[1][5] = fmaf(q1.z, w1, a1t[1][5]);
                a1t[2][0] = fmaf(q0.y, w2, a1t[2][0]);
                a1t[2][1] = fmaf(q0.z, w2, a1t[2][1]);
                a1t[2][2] = fmaf(q0.w, w2, a1t[2][2]);
                a1t[2][3] = fmaf(q1.x, w2, a1t[2][3]);
                a1t[2][4] = fmaf(q1.y, w2, a1t[2][4]);
                a1t[2][5] = fmaf(q1.z, w2, a1t[2][5]);
            }
            // fold into pz via W1 (columns are m1-active, no mask needed)
#pragma unroll
            for (int t = 0; t < 3; t++) {
                int p = lane + 32 * t;
                if (p < cmax) {
                    const float* w1r = W1s + cc[t] * 6;
                    float w6[6];
#pragma unroll
                    for (int j = 0; j < 6; j++) w6[j] = w1r[j];
#pragma unroll
                    for (int v = 0; v < 6; v++)
#pragma unroll
                        for (int j = 0; j < 6; j++) pz[v][j] = fmaf(a1t[t][v], w6[j], pz[v][j]);
                }
            }
        }
        // ---- tail pass (rare: cnt1 > 96) ----
        if (cnt1 > 96) {
            int cc[3]; float a1t[3][6];
#pragma unroll
            for (int t = 0; t < 3; t++) {
                int p = 96 + lane + 32 * t;
                cc[t] = (p < cnt1) ? c1w[p] : 0;
#pragma unroll
                for (int v = 0; v < 6; v++) a1t[t][v] = 0.f;
            }
            for (int c = 0; c < cnt2; c++) {
                const float4* q = (const float4*)(gw + c * 8);
                float4 q0 = q[0], q1 = q[1];
                const float* wp = W2s + __float_as_int(q0.x) * HID;
#pragma unroll
                for (int t = 0; t < 3; t++) {
                    float wv = wp[cc[t]];
                    a1t[t][0] = fmaf(q0.y, wv, a1t[t][0]);
                    a1t[t][1] = fmaf(q0.z, wv, a1t[t][1]);
                    a1t[t][2] = fmaf(q0.w, wv, a1t[t][2]);
                    a1t[t][3] = fmaf(q1.x, wv, a1t[t][3]);
                    a1t[t][4] = fmaf(q1.y, wv, a1t[t][4]);
                    a1t[t][5] = fmaf(q1.z, wv, a1t[t][5]);
                }
            }
#pragma unroll
            for (int t = 0; t < 3; t++) {
                int p = 96 + lane + 32 * t;
                if (p < cnt1) {
                    const float* w1r = W1s + cc[t] * 6;
                    float w6[6];
#pragma unroll
                    for (int j = 0; j < 6; j++) w6[j] = w1r[j];
#pragma unroll
                    for (int v = 0; v < 6; v++)
#pragma unroll
                        for (int j = 0; j < 6; j++) pz[v][j] = fmaf(a1t[t][v], w6[j], pz[v][j]);
                }
            }
        }

        // reduce pz across lanes
#pragma unroll
        for (int v = 0; v < 6; v++)
#pragma unroll
            for (int j = 0; j < 6; j++) {
                float x = pz[v][j];
#pragma unroll
                for (int off = 16; off > 0; off >>= 1) x += __shfl_xor_sync(0xffffffffu, x, off);
                pz[v][j] = x;
            }

        if (lane == 0) {
            float* vo = g_V + (size_t)b * 72;
#pragma unroll
            for (int v = 0; v < 6; v++)
#pragma unroll
                for (int j = 0; j < 6; j++) {
                    vo[v * 12 + j]     = Vw[v * 12 + 6 + j] + pz[v][j];
                    vo[v * 12 + 6 + j] = Vw[v * 12 + j] * es[j];
                }
        }
    }
}

// ---------------- deterministic Frobenius-norm reduction ----------------
__global__ void k_ssq_part() {
    float s = 0.f;
    for (int i = blockIdx.x * blockDim.x + threadIdx.x; i < B * 72; i += gridDim.x * blockDim.x) {
        float v = g_V[i]; s += v * v;
    }
    __shared__ float red[256];
    red[threadIdx.x] = s; __syncthreads();
    for (int o = 128; o > 0; o >>= 1) {
        if (threadIdx.x < o) red[threadIdx.x] += red[threadIdx.x + o];
        __syncthreads();
    }
    if (threadIdx.x == 0) g_part[blockIdx.x] = red[0];
}
__global__ void k_ssq_final() {
    __shared__ float red[256];
    red[threadIdx.x] = g_part[threadIdx.x]; __syncthreads();
    for (int o = 128; o > 0; o >>= 1) {
        if (threadIdx.x < o) red[threadIdx.x] += red[threadIdx.x + o];
        __syncthreads();
    }
    if (threadIdx.x == 0) g_ssq = red[0];
}

// ---------------- KL + log_prob ----------------
#define LIX(r, c) ((r) * ((r) + 1) / 2 + (c))

__global__ void __launch_bounds__(64) k_kl(
    const float* __restrict__ Wsym, const float* __restrict__ lvd,
    float* __restrict__ out)
{
    __shared__ float As[NB * 144];
    for (int i = threadIdx.x; i < NB * 144; i += 64) {
        int m = i / 144; int rc = i % 144; int r = rc / 12; int c = rc % 12;
        As[i] = Wsym[m * 144 + r * 12 + c] - Wsym[m * 144 + c * 12 + r];
    }
    __syncthreads();

    int b = blockIdx.x * 64 + threadIdx.x;
    if (b >= B) return;

    float zr[12]; float zz = 0.f;
#pragma unroll
    for (int i = 0; i < 12; i++) { zr[i] = g_zk[(size_t)b * 12 + i]; zz += zr[i] * zr[i]; }
    out[b] = g_ld[b] - 6.f * 1.8378770664093453f - 0.5f * zz;

    float scale = rsqrtf(g_ssq);
    float Jp[6][12];
#pragma unroll
    for (int v = 0; v < 6; v++)
#pragma unroll
        for (int i = 0; i < 12; i++) Jp[v][i] = g_V[(size_t)b * 72 + v * 12 + i] * scale;

    float Sql[78];
#pragma unroll
    for (int i = 0; i < 78; i++) Sql[i] = 0.f;
    float trq = 0.f, trpq = 0.f;

    for (int m = 0; m < NB; m++) {
        const float* Am = As + m * 144;
        float Jq[12];
#pragma unroll
        for (int jj = 0; jj < 12; jj++) {
            float a = 0.f;
#pragma unroll
            for (int i = 0; i < 12; i++) a = fmaf(zr[i], Am[jj * 12 + i], a);
            Jq[jj] = a; trq = fmaf(a, a, trq);
        }
#pragma unroll
        for (int n = 0; n < 12; n++)
#pragma unroll
            for (int mm = 0; mm <= n; mm++) Sql[LIX(n, mm)] = fmaf(Jq[n], Jq[mm], Sql[LIX(n, mm)]);
#pragma unroll
        for (int v = 0; v < 6; v++) {
            float d = 0.f;
#pragma unroll
            for (int i = 0; i < 12; i++) d = fmaf(Jp[v][i], Jq[i], d);
            trpq = fmaf(d, d, trpq);
        }
    }

    float Ml[21];
#pragma unroll
    for (int a = 0; a < 6; a++)
#pragma unroll
        for (int c = 0; c <= a; c++) {
            float acc = 0.f;
#pragma unroll
            for (int i = 0; i < 12; i++) acc = fmaf(Jp[a][i], Jp[c][i], acc);
            Ml[LIX(a, c)] = acc;
        }
#pragma unroll
    for (int d = 0; d < 6; d++) Ml[LIX(d, d)] += 1e-3f;
    float dm = 0.f;
#pragma unroll
    for (int d = 0; d < 6; d++) dm += Ml[LIX(d, d)];
    float normM = fmaxf(dm * (1.f / 6.f), 1e-6f);
#pragma unroll
    for (int d = 0; d < 6; d++) Ml[LIX(d, d)] += 1e-3f * normM;

    float D[12];
#pragma unroll
    for (int i = 0; i < 12; i++) D[i] = expf(-lvd[i]);
#pragma unroll
    for (int d = 0; d < 12; d++) Sql[LIX(d, d)] += D[d];
    float dh = 0.f;
#pragma unroll
    for (int d = 0; d < 12; d++) dh += Sql[LIX(d, d)];
    float normH = fmaxf(dh * (1.f / 12.f), 1e-6f);
#pragma unroll
    for (int d = 0; d < 12; d++) Sql[LIX(d, d)] += 1e-3f * normH;

    float Db[12], sumDb = 0.f;
#pragma unroll
    for (int i = 0; i < 12; i++) { Db[i] = D[i] + 1e-3f * normH; sumDb += Db[i]; }

    float trp = 0.f;
#pragma unroll
    for (int v = 0; v < 6; v++)
#pragma unroll
        for (int i = 0; i < 12; i++) trp = fmaf(Jp[v][i] * Jp[v][i], Db[i], trp);

    float trace = (1e-3f + 1e-3f * normM) * (sumDb + trq) + trp + trpq;

    float ldM = 0.f;
#pragma unroll
    for (int c = 0; c < 6; c++) {
        float d = Ml[LIX(c, c)];
#pragma unroll
        for (int kk = 0; kk < c; kk++) d -= Ml[LIX(c, kk)] * Ml[LIX(c, kk)];
        d = sqrtf(d); ldM += 2.f * logf(d);
        float inv = 1.f / d;
#pragma unroll
        for (int r = c + 1; r < 6; r++) {
            float a = Ml[LIX(r, c)];
#pragma unroll
            for (int kk = 0; kk < c; kk++) a -= Ml[LIX(r, kk)] * Ml[LIX(c, kk)];
            Ml[LIX(r, c)] = a * inv;
        }
    }
    float ldH = 0.f;
#pragma unroll
    for (int c = 0; c < 12; c++) {
        float d = Sql[LIX(c, c)];
#pragma unroll
        for (int kk = 0; kk < c; kk++) d -= Sql[LIX(c, kk)] * Sql[LIX(c, kk)];
        d = sqrtf(d); ldH += 2.f * logf(d);
        float inv = 1.f / d;
#pragma unroll
        for (int r = c + 1; r < 12; r++) {
            float a = Sql[LIX(r, c)];
#pragma unroll
            for (int kk = 0; kk < c; kk++) a -= Sql[LIX(r, kk)] * Sql[LIX(c, kk)];
            Sql[LIX(r, c)] = a * inv;
        }
    }

    float logdet_p = ldM + 6.f * (-6.907755278982137f);
    out[B + b] = 0.5f * (trace - logdet_p - ldH - 12.f);
}

// ---------------- host launcher ----------------
extern "C" void kernel_launch(void* const* d_in, const int* in_sizes, int n_in,
                              void* d_out, int out_size) {
    const float* y    = (const float*)d_in[0];
    const float* Jp   = (const float*)d_in[1];
    const float* W1   = (const float*)d_in[2];
    const float* b1   = (const float*)d_in[3];
    const float* W2   = (const float*)d_in[4];
    const float* b2   = (const float*)d_in[5];
    const float* W3   = (const float*)d_in[6];
    const float* b3   = (const float*)d_in[7];
    const float* Wsym = (const float*)d_in[8];
    const float* lvd  = (const float*)d_in[9];
    float* out = (float*)d_out;

    const int SMEM_INV = (HLF * HID + HID + HID * 193 + HID + 12 * HID + 16) * 4 + 16 * HID * 8;
    const int SMEM_VJP = (HID * HLF + HID * HID + 12 * HID + 8 * HID * 8 + 8 * HID + 8 * 72) * 4;
    cudaFuncSetAttribute(k_inv_layer, cudaFuncAttributeMaxDynamicSharedMemorySize, SMEM_INV);
    cudaFuncSetAttribute(k_vjp_layer, cudaFuncAttributeMaxDynamicSharedMemorySize, SMEM_VJP);

    k_init<<<256, 256>>>(y, Jp);

    for (int k = LAYERS - 1; k >= 0; k--) {
        k_inv_layer<<<152, 512, SMEM_INV>>>(
            W1 + (size_t)k * HID * HLF, b1 + (size_t)k * HID,
            W2 + (size_t)k * HID * HID, b2 + (size_t)k * HID,
            W3 + (size_t)k * 12 * HID,  b3 + (size_t)k * 12, k);
    }
    for (int k = LAYERS - 1; k >= 0; k--) {
        k_vjp_layer<<<152, 256, SMEM_VJP>>>(
            W1 + (size_t)k * HID * HLF,
            W2 + (size_t)k * HID * HID,
            W3 + (size_t)k * 12 * HID, k);
    }
    k_ssq_part<<<256, 256>>>();
    k_ssq_final<<<1, 256>>>();
    k_kl<<<(B + 63) / 64, 64>>>(Wsym, lvd, out);
}

// round 4
// speedup vs baseline: 1.6740x; 1.0574x over previous
#include <cuda_runtime.h>
#include <math.h>

#define B     16384
#define DIN   12
#define HLF   6
#define HID   192
#define LAYERS 24
#define NB    66
#define CAP2  128   // vjp per-warp g-list capacity (overflow handled exactly)

// ---------------- scratch (static device globals; no allocs) ----------------
__device__ float    g_zk[(LAYERS + 1) * B * DIN];
__device__ float    g_s [LAYERS * B * HLF];
__device__ unsigned g_m1[LAYERS * B * 6];
__device__ unsigned g_m2[LAYERS * B * 6];
__device__ float    g_V [B * 6 * DIN];
__device__ float    g_ld[B];
__device__ float    g_part[256];
__device__ float    g_ssq;

// ---------------- init ----------------
__global__ void k_init(const float* __restrict__ y, const float* __restrict__ Jp) {
    int i0 = blockIdx.x * blockDim.x + threadIdx.x;
    int st = gridDim.x * blockDim.x;
    for (int i = i0; i < B * 72; i += st) {
        g_V[i] = Jp[i];
        if (i < B * DIN) g_zk[LAYERS * B * DIN + i] = y[i];
        if (i < B)       g_ld[i] = 0.f;
    }
}

__device__ __forceinline__ float pick6(const float a[6], int i) {
    float r = a[0];
    if (i == 1) r = a[1];
    if (i == 2) r = a[2];
    if (i == 3) r = a[3];
    if (i == 4) r = a[4];
    if (i == 5) r = a[5];
    return r;
}
__device__ __forceinline__ unsigned pick6u(const unsigned a[6], int i) {
    unsigned r = a[0];
    if (i == 1) r = a[1];
    if (i == 2) r = a[2];
    if (i == 3) r = a[3];
    if (i == 4) r = a[4];
    if (i == 5) r = a[5];
    return r;
}

// ---------------- inverse coupling layer ----------------
__global__ void __launch_bounds__(512) k_inv_layer(
    const float* __restrict__ W1, const float* __restrict__ b1,
    const float* __restrict__ W2, const float* __restrict__ b2,
    const float* __restrict__ W3, const float* __restrict__ b3, int k)
{
    extern __shared__ float sm[];
    float*  W1t = sm;                 // [6][192]
    float*  b1s = W1t + HLF * HID;
    float*  W2t = b1s + HID;          // [192][193] transposed+pad
    float*  b2s = W2t + HID * 193;
    float*  W3s = b2s + HID;          // [12][192]
    float*  b3s = W3s + 12 * HID;
    float2* prs = (float2*)(b3s + 16);// 16 warps * 192

    int tid = threadIdx.x;
    for (int i = tid; i < HLF * HID; i += 512) { int r = i / HLF, j = i % HLF; W1t[j * HID + r] = W1[i]; }
    for (int i = tid; i < HID; i += 512) { b1s[i] = b1[i]; b2s[i] = b2[i]; }
    for (int i = tid; i < HID * HID; i += 512) { int r = i / HID, j = i % HID; W2t[j * 193 + r] = W2[i]; }
    for (int i = tid; i < 12 * HID; i += 512) W3s[i] = W3[i];
    if (tid < 12) b3s[tid] = b3[tid];
    __syncthreads();

    int lane = tid & 31, wip = tid >> 5;
    float2* pw = prs + wip * HID;
    unsigned lt = (1u << lane) - 1u;
    int w  = (blockIdx.x * 512 + tid) >> 5;
    int nw = gridDim.x * 16;

    for (int b = w; b < B; b += nw) {
        __syncwarp();
        const float* zin = g_zk + ((size_t)(k + 1) * B + b) * DIN;
        float z1[6], z2[6];
#pragma unroll
        for (int j = 0; j < 6; j++) { z1[j] = zin[6 + j]; z2[j] = zin[j]; }

        unsigned mm1[6];
        int base = 0;
#pragma unroll
        for (int i = 0; i < 6; i++) {
            int r = lane + 32 * i;
            float a = b1s[r];
#pragma unroll
            for (int j = 0; j < 6; j++) a = fmaf(W1t[j * HID + r], z1[j], a);
            unsigned m = __ballot_sync(0xffffffffu, a > 0.f);
            mm1[i] = m;
            if (m & (1u << lane)) {
                int pos = base + __popc(m & lt);
                pw[pos] = make_float2(a, __int_as_float(r * 193));  // pre-scaled row offset
            }
            base += __popc(m);
        }
        int cnt = base;
        __syncwarp();

        // layer 2: sparse j loop, unroll 4, dual accumulators
        float h2a[6], h2b[6];
#pragma unroll
        for (int i = 0; i < 6; i++) { h2a[i] = b2s[lane + 32 * i]; h2b[i] = 0.f; }
        int c = 0;
        for (; c + 4 <= cnt; c += 4) {
            float2 p0 = pw[c], p1 = pw[c + 1], p2 = pw[c + 2], p3 = pw[c + 3];
            const float* w0 = W2t + __float_as_int(p0.y) + lane;
            const float* w1 = W2t + __float_as_int(p1.y) + lane;
            const float* w2 = W2t + __float_as_int(p2.y) + lane;
            const float* w3 = W2t + __float_as_int(p3.y) + lane;
#pragma unroll
            for (int i = 0; i < 6; i++) {
                h2a[i] = fmaf(w1[32 * i], p1.x, fmaf(w0[32 * i], p0.x, h2a[i]));
                h2b[i] = fmaf(w3[32 * i], p3.x, fmaf(w2[32 * i], p2.x, h2b[i]));
            }
        }
        for (; c < cnt; c++) {
            float2 p0 = pw[c];
            const float* w0 = W2t + __float_as_int(p0.y) + lane;
#pragma unroll
            for (int i = 0; i < 6; i++) h2a[i] = fmaf(w0[32 * i], p0.x, h2a[i]);
        }
        unsigned mm2[6];
#pragma unroll
        for (int i = 0; i < 6; i++) {
            h2a[i] += h2b[i];
            mm2[i] = __ballot_sync(0xffffffffu, h2a[i] > 0.f);
            h2a[i] = fmaxf(h2a[i], 0.f);
        }

        float pp[12];
#pragma unroll
        for (int o = 0; o < 12; o++) {
            float a = 0.f;
#pragma unroll
            for (int i = 0; i < 6; i++) a = fmaf(W3s[o * HID + lane + 32 * i], h2a[i], a);
#pragma unroll
            for (int off = 16; off > 0; off >>= 1) a += __shfl_xor_sync(0xffffffffu, a, off);
            pp[o] = a;
        }

        float ssum = 0.f, sv[6], znew[6];
#pragma unroll
        for (int j = 0; j < 6; j++) {
            float sh = pp[2 * j] + b3s[2 * j];
            float sr = pp[2 * j + 1] + b3s[2 * j + 1];
            float s  = 2.f * tanhf(0.5f * sr);
            sv[j] = s; ssum += s;
            znew[j] = (z2[j] - sh) * expf(-s);
        }
        {
            float* zo = g_zk + ((size_t)k * B + b) * DIN;
            if (lane < 12) {
                float v = (lane < 6) ? pick6(z1, lane) : pick6(znew, lane - 6);
                zo[lane] = v;
            }
            float* so = g_s + ((size_t)k * B + b) * HLF;
            if (lane >= 16 && lane < 22) so[lane - 16] = pick6(sv, lane - 16);
            unsigned* m1o = g_m1 + ((size_t)k * B + b) * 6;
            unsigned* m2o = g_m2 + ((size_t)k * B + b) * 6;
            if (lane >= 24 && lane < 30) m1o[lane - 24] = pick6u(mm1, lane - 24);
            if (lane >= 8 && lane < 14)  m2o[lane - 8]  = pick6u(mm2, lane - 8);
            if (lane == 31) g_ld[b] -= ssum;
        }
    }
}

// ---------------- VJP layer: dual-sided sparsity, 16 warps/SM ----------------
// per-warp scratch block: 960 floats:
//   [0,768)   gpair: 128 entries * 3 float2 (g0..g5)
//   [768,840) Vw: 72 floats
//   [840,904) gi: 128 ushort (pre-scaled j*192)
//   [904,952) c1w: 192 uchar (m1-active columns)
#define VJP_WSTRIDE 960

__global__ void __launch_bounds__(512) k_vjp_layer(
    const float* __restrict__ W1, const float* __restrict__ W2,
    const float* __restrict__ W3, int k)
{
    extern __shared__ float sm[];
    float* W1s = sm;                    // [192][6]
    float* W2s = W1s + HID * HLF;       // [192][192] row-major
    float* W3s = W2s + HID * HID;       // [12][192]
    float* wsc = W3s + 12 * HID;        // 16 warp scratch blocks

    int tid = threadIdx.x;
    for (int i = tid; i < HID * HLF; i += 512) W1s[i] = W1[i];
    for (int i = tid; i < HID * HID; i += 512) W2s[i] = W2[i];
    for (int i = tid; i < 12 * HID; i += 512)  W3s[i] = W3[i];
    __syncthreads();

    int lane = tid & 31, wip = tid >> 5;
    float*  wb   = wsc + wip * VJP_WSTRIDE;
    float2* gpair = (float2*)wb;
    float*  Vw   = wb + 768;
    unsigned short* gi = (unsigned short*)(wb + 840);
    unsigned char*  c1w = (unsigned char*)(wb + 904);
    unsigned lt = (1u << lane) - 1u;
    int w  = (blockIdx.x * 512 + tid) >> 5;
    int nw = gridDim.x * 16;

    for (int b = w; b < B; b += nw) {
        __syncwarp();
        for (int t = lane; t < 72; t += 32) Vw[t] = g_V[(size_t)b * 72 + t];

        float es[6], fac[6];
        const float* sp = g_s  + ((size_t)k * B + b) * HLF;
        const float* zp = g_zk + ((size_t)k * B + b) * DIN;
#pragma unroll
        for (int j = 0; j < 6; j++) {
            float s = sp[j]; float e = expf(s); es[j] = e;
            float t2 = 0.5f * s;
            fac[j] = zp[6 + j] * e * (1.f - t2 * t2);
        }
        unsigned m2v[6];
        const unsigned* m1p = g_m1 + ((size_t)k * B + b) * 6;
        const unsigned* m2p = g_m2 + ((size_t)k * B + b) * 6;

        // build m1-active column list (uchar)
        int cnt1;
        {
            int base1 = 0;
#pragma unroll
            for (int i = 0; i < 6; i++) {
                unsigned m = m1p[i];
                if (m & (1u << lane)) c1w[base1 + __popc(m & lt)] = (unsigned char)(lane + 32 * i);
                base1 += __popc(m);
            }
            cnt1 = base1;
        }
#pragma unroll
        for (int i = 0; i < 6; i++) m2v[i] = m2p[i];

        // step 1: acc[v][kk] = (g_prm @ W3) at j = lane+32kk
        float acc[6][6];
#pragma unroll
        for (int v = 0; v < 6; v++)
#pragma unroll
            for (int kk = 0; kk < 6; kk++) acc[v][kk] = 0.f;
#pragma unroll
        for (int o = 0; o < 12; o++) {
            int j = o >> 1;
            float wv[6];
#pragma unroll
            for (int kk = 0; kk < 6; kk++) wv[kk] = W3s[o * HID + lane + 32 * kk];
#pragma unroll
            for (int v = 0; v < 6; v++) {
                float g = Vw[v * 12 + j];
                if (o & 1) g *= fac[j];
#pragma unroll
                for (int kk = 0; kk < 6; kk++) acc[v][kk] = fmaf(g, wv[kk], acc[v][kk]);
            }
        }

        // compact m2-active rows of g_h2 (capacity CAP2, exact overflow handling)
        int pre = 0;
#pragma unroll
        for (int i = 0; i < 6; i++) pre += __popc(m2v[i]);
        bool hasov = (pre > CAP2);
        unsigned ovm[6];
        int base2 = 0;
#pragma unroll
        for (int kk = 0; kk < 6; kk++) {
            unsigned m = m2v[kk];
            unsigned keep = m;
            if (hasov) {
                int pc = __popc(m);
                int ovc = base2 + pc - CAP2;
                if (ovc > 0) {
                    if (ovc > pc) ovc = pc;
                    for (int t = 0; t < ovc; t++) keep &= ~(0x80000000u >> __clz(keep));
                }
            }
            ovm[kk] = m ^ keep;
            if (keep & (1u << lane)) {
                int pos = base2 + __popc(keep & lt);
                gi[pos] = (unsigned short)((lane + 32 * kk) * HID);
                gpair[pos * 3 + 0] = make_float2(acc[0][kk], acc[1][kk]);
                gpair[pos * 3 + 1] = make_float2(acc[2][kk], acc[3][kk]);
                gpair[pos * 3 + 2] = make_float2(acc[4][kk], acc[5][kk]);
            }
            base2 += __popc(keep);
        }
        int cnt2 = base2;
        __syncwarp();

        float pz[6][6];
#pragma unroll
        for (int v = 0; v < 6; v++)
#pragma unroll
            for (int j = 0; j < 6; j++) pz[v][j] = 0.f;

        // ---- main pass: compacted output columns p = lane + 32t, t<3 ----
        {
            int cmax = cnt1 < 96 ? cnt1 : 96;
            int cc[3]; float a1t[3][6];
#pragma unroll
            for (int t = 0; t < 3; t++) {
                int p = lane + 32 * t;
                cc[t] = (p < cmax) ? (int)c1w[p] : 0;
#pragma unroll
                for (int v = 0; v < 6; v++) a1t[t][v] = 0.f;
            }
            for (int c = 0; c < cnt2; c++) {
                float2 ga = gpair[c * 3], gb = gpair[c * 3 + 1], gc = gpair[c * 3 + 2];
                const float* wp = W2s + gi[c];
                float w0 = wp[cc[0]], w1 = wp[cc[1]], w2 = wp[cc[2]];
                a1t[0][0] = fmaf(ga.x, w0, a1t[0][0]);
                a1t[0][1] = fmaf(ga.y, w0, a1t[0][1]);
                a1t[0][2] = fmaf(gb.x, w0, a1t[0][2]);
                a1t[0][3] = fmaf(gb.y, w0, a1t[0][3]);
                a1t[0][4] = fmaf(gc.x, w0, a1t[0][4]);
                a1t[0][5] = fmaf(gc.y, w0, a1t[0][5]);
                a1t[1][0] = fmaf(ga.x, w1, a1t[1][0]);
                a1t[1][1] = fmaf(ga.y, w1, a1t[1][1]);
                a1t[1][2] = fmaf(gb.x, w1, a1t[1][2]);
                a1t[1][3] = fmaf(gb.y, w1, a1t[1][3]);
                a1t[1][4] = fmaf(gc.x, w1, a1t[1][4]);
                a1t[1][5] = fmaf(gc.y, w1, a1t[1][5]);
                a1t[2][0] = fmaf(ga.x, w2, a1t[2][0]);
                a1t[2][1] = fmaf(ga.y, w2, a1t[2][1]);
                a1t[2][2] = fmaf(gb.x, w2, a1t[2][2]);
                a1t[2][3] = fmaf(gb.y, w2, a1t[2][3]);
                a1t[2][4] = fmaf(gc.x, w2, a1t[2][4]);
                a1t[2][5] = fmaf(gc.y, w2, a1t[2][5]);
            }
            if (hasov) {  // exact fallback for overflow entries (ultra-rare)
#pragma unroll
                for (int kk = 0; kk < 6; kk++) {
                    unsigned ov = ovm[kk];
                    while (ov) {
                        int src = __ffs(ov) - 1; ov &= ov - 1;
                        float g0 = __shfl_sync(0xffffffffu, acc[0][kk], src);
                        float g1 = __shfl_sync(0xffffffffu, acc[1][kk], src);
                        float g2 = __shfl_sync(0xffffffffu, acc[2][kk], src);
                        float g3 = __shfl_sync(0xffffffffu, acc[3][kk], src);
                        float g4 = __shfl_sync(0xffffffffu, acc[4][kk], src);
                        float g5 = __shfl_sync(0xffffffffu, acc[5][kk], src);
                        const float* wp = W2s + (src + 32 * kk) * HID;
#pragma unroll
                        for (int t = 0; t < 3; t++) {
                            float wv = wp[cc[t]];
                            a1t[t][0] = fmaf(g0, wv, a1t[t][0]);
                            a1t[t][1] = fmaf(g1, wv, a1t[t][1]);
                            a1t[t][2] = fmaf(g2, wv, a1t[t][2]);
                            a1t[t][3] = fmaf(g3, wv, a1t[t][3]);
                            a1t[t][4] = fmaf(g4, wv, a1t[t][4]);
                            a1t[t][5] = fmaf(g5, wv, a1t[t][5]);
                        }
                    }
                }
            }
#pragma unroll
            for (int t = 0; t < 3; t++) {
                int p = lane + 32 * t;
                if (p < cmax) {
                    const float* w1r = W1s + cc[t] * 6;
                    float w6[6];
#pragma unroll
                    for (int j = 0; j < 6; j++) w6[j] = w1r[j];
#pragma unroll
                    for (int v = 0; v < 6; v++)
#pragma unroll
                        for (int j = 0; j < 6; j++) pz[v][j] = fmaf(a1t[t][v], w6[j], pz[v][j]);
                }
            }
        }
        // ---- tail pass (cnt1 > 96) ----
        if (cnt1 > 96) {
            int cc[3]; float a1t[3][6];
#pragma unroll
            for (int t = 0; t < 3; t++) {
                int p = 96 + lane + 32 * t;
                cc[t] = (p < cnt1) ? (int)c1w[p] : 0;
#pragma unroll
                for (int v = 0; v < 6; v++) a1t[t][v] = 0.f;
            }
            for (int c = 0; c < cnt2; c++) {
                float2 ga = gpair[c * 3], gb = gpair[c * 3 + 1], gc = gpair[c * 3 + 2];
                const float* wp = W2s + gi[c];
#pragma unroll
                for (int t = 0; t < 3; t++) {
                    float wv = wp[cc[t]];
                    a1t[t][0] = fmaf(ga.x, wv, a1t[t][0]);
                    a1t[t][1] = fmaf(ga.y, wv, a1t[t][1]);
                    a1t[t][2] = fmaf(gb.x, wv, a1t[t][2]);
                    a1t[t][3] = fmaf(gb.y, wv, a1t[t][3]);
                    a1t[t][4] = fmaf(gc.x, wv, a1t[t][4]);
                    a1t[t][5] = fmaf(gc.y, wv, a1t[t][5]);
                }
            }
            if (hasov) {
#pragma unroll
                for (int kk = 0; kk < 6; kk++) {
                    unsigned ov = ovm[kk];
                    while (ov) {
                        int src = __ffs(ov) - 1; ov &= ov - 1;
                        float g0 = __shfl_sync(0xffffffffu, acc[0][kk], src);
                        float g1 = __shfl_sync(0xffffffffu, acc[1][kk], src);
                        float g2 = __shfl_sync(0xffffffffu, acc[2][kk], src);
                        float g3 = __shfl_sync(0xffffffffu, acc[3][kk], src);
                        float g4 = __shfl_sync(0xffffffffu, acc[4][kk], src);
                        float g5 = __shfl_sync(0xffffffffu, acc[5][kk], src);
                        const float* wp = W2s + (src + 32 * kk) * HID;
#pragma unroll
                        for (int t = 0; t < 3; t++) {
                            float wv = wp[cc[t]];
                            a1t[t][0] = fmaf(g0, wv, a1t[t][0]);
                            a1t[t][1] = fmaf(g1, wv, a1t[t][1]);
                            a1t[t][2] = fmaf(g2, wv, a1t[t][2]);
                            a1t[t][3] = fmaf(g3, wv, a1t[t][3]);
                            a1t[t][4] = fmaf(g4, wv, a1t[t][4]);
                            a1t[t][5] = fmaf(g5, wv, a1t[t][5]);
                        }
                    }
                }
            }
#pragma unroll
            for (int t = 0; t < 3; t++) {
                int p = 96 + lane + 32 * t;
                if (p < cnt1) {
                    const float* w1r = W1s + cc[t] * 6;
                    float w6[6];
#pragma unroll
                    for (int j = 0; j < 6; j++) w6[j] = w1r[j];
#pragma unroll
                    for (int v = 0; v < 6; v++)
#pragma unroll
                        for (int j = 0; j < 6; j++) pz[v][j] = fmaf(a1t[t][v], w6[j], pz[v][j]);
                }
            }
        }

        // reduce pz across lanes
#pragma unroll
        for (int v = 0; v < 6; v++)
#pragma unroll
            for (int j = 0; j < 6; j++) {
                float x = pz[v][j];
#pragma unroll
                for (int off = 16; off > 0; off >>= 1) x += __shfl_xor_sync(0xffffffffu, x, off);
                pz[v][j] = x;
            }

        if (lane == 0) {
            float* vo = g_V + (size_t)b * 72;
#pragma unroll
            for (int v = 0; v < 6; v++)
#pragma unroll
                for (int j = 0; j < 6; j++) {
                    vo[v * 12 + j]     = Vw[v * 12 + 6 + j] + pz[v][j];
                    vo[v * 12 + 6 + j] = Vw[v * 12 + j] * es[j];
                }
        }
    }
}

// ---------------- deterministic Frobenius-norm reduction ----------------
__global__ void k_ssq_part() {
    float s = 0.f;
    for (int i = blockIdx.x * blockDim.x + threadIdx.x; i < B * 72; i += gridDim.x * blockDim.x) {
        float v = g_V[i]; s += v * v;
    }
    __shared__ float red[256];
    red[threadIdx.x] = s; __syncthreads();
    for (int o = 128; o > 0; o >>= 1) {
        if (threadIdx.x < o) red[threadIdx.x] += red[threadIdx.x + o];
        __syncthreads();
    }
    if (threadIdx.x == 0) g_part[blockIdx.x] = red[0];
}
__global__ void k_ssq_final() {
    __shared__ float red[256];
    red[threadIdx.x] = g_part[threadIdx.x]; __syncthreads();
    for (int o = 128; o > 0; o >>= 1) {
        if (threadIdx.x < o) red[threadIdx.x] += red[threadIdx.x + o];
        __syncthreads();
    }
    if (threadIdx.x == 0) g_ssq = red[0];
}

// ---------------- KL + log_prob ----------------
#define LIX(r, c) ((r) * ((r) + 1) / 2 + (c))

__global__ void __launch_bounds__(64) k_kl(
    const float* __restrict__ Wsym, const float* __restrict__ lvd,
    float* __restrict__ out)
{
    __shared__ float As[NB * 144];
    for (int i = threadIdx.x; i < NB * 144; i += 64) {
        int m = i / 144; int rc = i % 144; int r = rc / 12; int c = rc % 12;
        As[i] = Wsym[m * 144 + r * 12 + c] - Wsym[m * 144 + c * 12 + r];
    }
    __syncthreads();

    int b = blockIdx.x * 64 + threadIdx.x;
    if (b >= B) return;

    float zr[12]; float zz = 0.f;
#pragma unroll
    for (int i = 0; i < 12; i++) { zr[i] = g_zk[(size_t)b * 12 + i]; zz += zr[i] * zr[i]; }
    out[b] = g_ld[b] - 6.f * 1.8378770664093453f - 0.5f * zz;

    float scale = rsqrtf(g_ssq);
    float Jp[6][12];
#pragma unroll
    for (int v = 0; v < 6; v++)
#pragma unroll
        for (int i = 0; i < 12; i++) Jp[v][i] = g_V[(size_t)b * 72 + v * 12 + i] * scale;

    float Sql[78];
#pragma unroll
    for (int i = 0; i < 78; i++) Sql[i] = 0.f;
    float trq = 0.f, trpq = 0.f;

    for (int m = 0; m < NB; m++) {
        const float* Am = As + m * 144;
        float Jq[12];
#pragma unroll
        for (int jj = 0; jj < 12; jj++) {
            float a = 0.f;
#pragma unroll
            for (int i = 0; i < 12; i++) a = fmaf(zr[i], Am[jj * 12 + i], a);
            Jq[jj] = a; trq = fmaf(a, a, trq);
        }
#pragma unroll
        for (int n = 0; n < 12; n++)
#pragma unroll
            for (int mm = 0; mm <= n; mm++) Sql[LIX(n, mm)] = fmaf(Jq[n], Jq[mm], Sql[LIX(n, mm)]);
#pragma unroll
        for (int v = 0; v < 6; v++) {
            float d = 0.f;
#pragma unroll
            for (int i = 0; i < 12; i++) d = fmaf(Jp[v][i], Jq[i], d);
            trpq = fmaf(d, d, trpq);
        }
    }

    float Ml[21];
#pragma unroll
    for (int a = 0; a < 6; a++)
#pragma unroll
        for (int c = 0; c <= a; c++) {
            float acc = 0.f;
#pragma unroll
            for (int i = 0; i < 12; i++) acc = fmaf(Jp[a][i], Jp[c][i], acc);
            Ml[LIX(a, c)] = acc;
        }
#pragma unroll
    for (int d = 0; d < 6; d++) Ml[LIX(d, d)] += 1e-3f;
    float dm = 0.f;
#pragma unroll
    for (int d = 0; d < 6; d++) dm += Ml[LIX(d, d)];
    float normM = fmaxf(dm * (1.f / 6.f), 1e-6f);
#pragma unroll
    for (int d = 0; d < 6; d++) Ml[LIX(d, d)] += 1e-3f * normM;

    float D[12];
#pragma unroll
    for (int i = 0; i < 12; i++) D[i] = expf(-lvd[i]);
#pragma unroll
    for (int d = 0; d < 12; d++) Sql[LIX(d, d)] += D[d];
    float dh = 0.f;
#pragma unroll
    for (int d = 0; d < 12; d++) dh += Sql[LIX(d, d)];
    float normH = fmaxf(dh * (1.f / 12.f), 1e-6f);
#pragma unroll
    for (int d = 0; d < 12; d++) Sql[LIX(d, d)] += 1e-3f * normH;

    float Db[12], sumDb = 0.f;
#pragma unroll
    for (int i = 0; i < 12; i++) { Db[i] = D[i] + 1e-3f * normH; sumDb += Db[i]; }

    float trp = 0.f;
#pragma unroll
    for (int v = 0; v < 6; v++)
#pragma unroll
        for (int i = 0; i < 12; i++) trp = fmaf(Jp[v][i] * Jp[v][i], Db[i], trp);

    float trace = (1e-3f + 1e-3f * normM) * (sumDb + trq) + trp + trpq;

    float ldM = 0.f;
#pragma unroll
    for (int c = 0; c < 6; c++) {
        float d = Ml[LIX(c, c)];
#pragma unroll
        for (int kk = 0; kk < c; kk++) d -= Ml[LIX(c, kk)] * Ml[LIX(c, kk)];
        d = sqrtf(d); ldM += 2.f * logf(d);
        float inv = 1.f / d;
#pragma unroll
        for (int r = c + 1; r < 6; r++) {
            float a = Ml[LIX(r, c)];
#pragma unroll
            for (int kk = 0; kk < c; kk++) a -= Ml[LIX(r, kk)] * Ml[LIX(c, kk)];
            Ml[LIX(r, c)] = a * inv;
        }
    }
    float ldH = 0.f;
#pragma unroll
    for (int c = 0; c < 12; c++) {
        float d = Sql[LIX(c, c)];
#pragma unroll
        for (int kk = 0; kk < c; kk++) d -= Sql[LIX(c, kk)] * Sql[LIX(c, kk)];
        d = sqrtf(d); ldH += 2.f * logf(d);
        float inv = 1.f / d;
#pragma unroll
        for (int r = c + 1; r < 12; r++) {
            float a = Sql[LIX(r, c)];
#pragma unroll
            for (int kk = 0; kk < c; kk++) a -= Sql[LIX(r, kk)] * Sql[LIX(c, kk)];
            Sql[LIX(r, c)] = a * inv;
        }
    }

    float logdet_p = ldM + 6.f * (-6.907755278982137f);
    out[B + b] = 0.5f * (trace - logdet_p - ldH - 12.f);
}

// ---------------- host launcher ----------------
extern "C" void kernel_launch(void* const* d_in, const int* in_sizes, int n_in,
                              void* d_out, int out_size) {
    const float* y    = (const float*)d_in[0];
    const float* Jp   = (const float*)d_in[1];
    const float* W1   = (const float*)d_in[2];
    const float* b1   = (const float*)d_in[3];
    const float* W2   = (const float*)d_in[4];
    const float* b2   = (const float*)d_in[5];
    const float* W3   = (const float*)d_in[6];
    const float* b3   = (const float*)d_in[7];
    const float* Wsym = (const float*)d_in[8];
    const float* lvd  = (const float*)d_in[9];
    float* out = (float*)d_out;

    const int SMEM_INV = (HLF * HID + HID + HID * 193 + HID + 12 * HID + 16) * 4 + 16 * HID * 8;
    const int SMEM_VJP = (HID * HLF + HID * HID + 12 * HID + 16 * VJP_WSTRIDE) * 4;
    cudaFuncSetAttribute(k_inv_layer, cudaFuncAttributeMaxDynamicSharedMemorySize, SMEM_INV);
    cudaFuncSetAttribute(k_vjp_layer, cudaFuncAttributeMaxDynamicSharedMemorySize, SMEM_VJP);

    k_init<<<256, 256>>>(y, Jp);

    for (int k = LAYERS - 1; k >= 0; k--) {
        k_inv_layer<<<152, 512, SMEM_INV>>>(
            W1 + (size_t)k * HID * HLF, b1 + (size_t)k * HID,
            W2 + (size_t)k * HID * HID, b2 + (size_t)k * HID,
            W3 + (size_t)k * 12 * HID,  b3 + (size_t)k * 12, k);
    }
    for (int k = LAYERS - 1; k >= 0; k--) {
        k_vjp_layer<<<152, 512, SMEM_VJP>>>(
            W1 + (size_t)k * HID * HLF,
            W2 + (size_t)k * HID * HID,
            W3 + (size_t)k * 12 * HID, k);
    }
    k_ssq_part<<<256, 256>>>();
    k_ssq_final<<<1, 256>>>();
    k_kl<<<(B + 63) / 64, 64>>>(Wsym, lvd, out);
}

// round 5
// speedup vs baseline: 1.8842x; 1.1255x over previous
#include <cuda_runtime.h>
#include <math.h>

#define B      16384
#define DIN    12
#define HID    192
#define LAYERS 24
#define NB     66
#define CAP2   120
#define W2STR  194

// ---------------- scratch ----------------
__device__ float g_zk[(LAYERS + 1) * B * DIN];
__device__ float g_V [B * 72];
__device__ float g_ld[B];
__device__ float g_part[256];
__device__ float g_ssq;

// ---------------- f32x2 packed FMA ----------------
union F2U { float2 f; unsigned long long u; };
__device__ __forceinline__ float2 ffma2(float2 a, float2 b, float2 c) {
    F2U A, Bv, C, D; A.f = a; Bv.f = b; C.f = c;
    asm("fma.rn.f32x2 %0,%1,%2,%3;" : "=l"(D.u) : "l"(A.u), "l"(Bv.u), "l"(C.u));
    return D.f;
}

__device__ __forceinline__ float pick6(const float a[6], int i) {
    float r = a[0];
    if (i == 1) r = a[1];
    if (i == 2) r = a[2];
    if (i == 3) r = a[3];
    if (i == 4) r = a[4];
    if (i == 5) r = a[5];
    return r;
}

// ---------------- init ----------------
__global__ void k_init(const float* __restrict__ y, const float* __restrict__ Jp) {
    int i0 = blockIdx.x * blockDim.x + threadIdx.x;
    int st = gridDim.x * blockDim.x;
    for (int i = i0; i < B * 72; i += st) {
        g_V[i] = Jp[i];
        if (i < B * DIN) g_zk[LAYERS * B * DIN + i] = y[i];
        if (i < B)       g_ld[i] = 0.f;
    }
}

// smem float offsets
#define OFF_W2T  0
#define OFF_W3   37248
#define OFF_W1   39552
#define OFF_B1   40704
#define OFF_B2   40896
#define OFF_B3   41088
#define OFF_WARP 41104
#define WSTRIDE  904
// per-warp block: gpair [0,720) (also pw), Vw [720,792), c1w uchar [792,840), gi ushort [840,904)

// ---------------- fused inverse + VJP layer ----------------
__global__ void __launch_bounds__(512) k_fused(
    const float* __restrict__ W1, const float* __restrict__ b1,
    const float* __restrict__ W2, const float* __restrict__ b2,
    const float* __restrict__ W3, const float* __restrict__ b3, int k)
{
    extern __shared__ float sm[];
    float* W2T = sm + OFF_W2T;   // [192][194]: W2T[j*194+c] = W2[c][j]
    float* W3s = sm + OFF_W3;    // [12][192] row-major (float2-viewable)
    float* W1s = sm + OFF_W1;    // [192][6]
    float* b1s = sm + OFF_B1;
    float* b2s = sm + OFF_B2;
    float* b3s = sm + OFF_B3;

    int tid = threadIdx.x;
    for (int i = tid; i < HID * HID; i += 512) {
        int cout = i / HID, jin = i % HID;
        W2T[jin * W2STR + cout] = W2[i];
    }
    for (int i = tid; i < 12 * HID; i += 512) W3s[i] = W3[i];
    for (int i = tid; i < HID * 6; i += 512)  W1s[i] = W1[i];
    for (int i = tid; i < HID; i += 512) { b1s[i] = b1[i]; b2s[i] = b2[i]; }
    if (tid < 12) b3s[tid] = b3[tid];
    __syncthreads();

    int lane = tid & 31, wip = tid >> 5;
    float* wb = sm + OFF_WARP + wip * WSTRIDE;
    float2* pw   = (float2*)wb;          // inv h1 list, then vjp gpair
    float*  Vw   = wb + 720;
    unsigned char*  c1w = (unsigned char*)(wb + 792);
    unsigned short* gi  = (unsigned short*)(wb + 840);
    unsigned lt = (1u << lane) - 1u;

    int w  = (blockIdx.x * 512 + tid) >> 5;
    int nw = gridDim.x * 16;

    for (int b = w; b < B; b += nw) {
        // =========================== INVERSE PHASE ===========================
        __syncwarp();
        const float* zin = g_zk + ((size_t)(k + 1) * B + b) * DIN;
        float z1[6], z2[6];
#pragma unroll
        for (int j = 0; j < 6; j++) { z1[j] = zin[6 + j]; z2[j] = zin[j]; }
        float2 z1p[3];
#pragma unroll
        for (int q = 0; q < 3; q++) z1p[q] = make_float2(z1[2 * q], z1[2 * q + 1]);

        // L1: rows r = lane + 32i
        unsigned mm1[6];
        int base = 0;
#pragma unroll
        for (int i = 0; i < 6; i++) {
            int r = lane + 32 * i;
            const float2* w1r = (const float2*)(W1s + r * 6);
            float2 t0 = ffma2(w1r[0], z1p[0], make_float2(b1s[r], 0.f));
            t0 = ffma2(w1r[1], z1p[1], t0);
            t0 = ffma2(w1r[2], z1p[2], t0);
            float a = t0.x + t0.y;
            unsigned m = __ballot_sync(0xffffffffu, a > 0.f);
            mm1[i] = m;
            if ((m >> lane) & 1u) {
                int pos = base + __popc(m & lt);
                pw[pos] = make_float2(a, __int_as_float(r * W2STR));
                c1w[pos] = (unsigned char)r;
            }
            base += __popc(m);
        }
        int cnt1 = base;
        __syncwarp();

        // L2: h2 pairs, cols (64q+2*lane, +1)
        float2 h2p[3], h2q[3];
#pragma unroll
        for (int q = 0; q < 3; q++) {
            h2p[q] = ((const float2*)b2s)[q * 32 + lane];
            h2q[q] = make_float2(0.f, 0.f);
        }
        {
            int c = 0;
            for (; c + 2 <= cnt1; c += 2) {
                float2 p0 = pw[c], p1 = pw[c + 1];
                int r0 = __float_as_int(p0.y), r1 = __float_as_int(p1.y);
                float2 h0 = make_float2(p0.x, p0.x), h1v = make_float2(p1.x, p1.x);
#pragma unroll
                for (int q = 0; q < 3; q++) {
                    float2 wa = *(const float2*)(W2T + r0 + 64 * q + 2 * lane);
                    float2 wbv = *(const float2*)(W2T + r1 + 64 * q + 2 * lane);
                    h2p[q] = ffma2(wa, h0, h2p[q]);
                    h2q[q] = ffma2(wbv, h1v, h2q[q]);
                }
            }
            if (c < cnt1) {
                float2 p0 = pw[c];
                int r0 = __float_as_int(p0.y);
                float2 h0 = make_float2(p0.x, p0.x);
#pragma unroll
                for (int q = 0; q < 3; q++) {
                    float2 wa = *(const float2*)(W2T + r0 + 64 * q + 2 * lane);
                    h2p[q] = ffma2(wa, h0, h2p[q]);
                }
            }
        }
        unsigned mm2[6];
        float2 h2r[3];
#pragma unroll
        for (int q = 0; q < 3; q++) {
            float hx = h2p[q].x + h2q[q].x;
            float hy = h2p[q].y + h2q[q].y;
            mm2[2 * q]     = __ballot_sync(0xffffffffu, hx > 0.f);
            mm2[2 * q + 1] = __ballot_sync(0xffffffffu, hy > 0.f);
            h2r[q] = make_float2(fmaxf(hx, 0.f), fmaxf(hy, 0.f));
        }

        // L3
        float pp[12];
#pragma unroll
        for (int o = 0; o < 12; o++) {
            float2 acc = make_float2(0.f, 0.f);
#pragma unroll
            for (int q = 0; q < 3; q++)
                acc = ffma2(((const float2*)(W3s + o * HID))[q * 32 + lane], h2r[q], acc);
            float a = acc.x + acc.y;
#pragma unroll
            for (int off = 16; off > 0; off >>= 1) a += __shfl_xor_sync(0xffffffffu, a, off);
            pp[o] = a;
        }

        // epilogue: s, znew, es, fac
        float ssum = 0.f, znew[6], es[6], fac[6];
#pragma unroll
        for (int j = 0; j < 6; j++) {
            float sh = pp[2 * j] + b3s[2 * j];
            float sr = pp[2 * j + 1] + b3s[2 * j + 1];
            float s  = 2.f * tanhf(0.5f * sr);
            ssum += s;
            float em = expf(-s);
            znew[j] = (z2[j] - sh) * em;
            es[j]   = expf(s);
            float t2 = 0.5f * s;
            fac[j]  = znew[j] * es[j] * (1.f - t2 * t2);
        }
        {
            float* zo = g_zk + ((size_t)k * B + b) * DIN;
            if (lane < 12) zo[lane] = (lane < 6) ? pick6(z1, lane) : pick6(znew, lane - 6);
            if (lane == 31) g_ld[b] -= ssum;
        }

        // ============================= VJP PHASE =============================
        for (int t = lane; t < 72; t += 32) Vw[t] = g_V[(size_t)b * 72 + t];

        // read m1-compact offsets BEFORE gpair clobbers pw
        int cmax = cnt1 < 128 ? cnt1 : 128;
        int ccf[4];
#pragma unroll
        for (int t = 0; t < 4; t++) {
            int p = lane + 32 * t;
            ccf[t] = (p < cmax) ? __float_as_int(pw[p].y) : 0;
        }
        __syncwarp();

        // step 1: accp[v][q] (f32x2 halves = cols 64q+2*lane, +1)
        float2 accp[6][3];
#pragma unroll
        for (int v = 0; v < 6; v++)
#pragma unroll
            for (int q = 0; q < 3; q++) accp[v][q] = make_float2(0.f, 0.f);
#pragma unroll
        for (int j = 0; j < 6; j++) {
            float2 gv2[6], gf2[6];
#pragma unroll
            for (int v = 0; v < 6; v++) {
                float g = Vw[v * 12 + j];
                gv2[v] = make_float2(g, g);
                float gf = g * fac[j];
                gf2[v] = make_float2(gf, gf);
            }
#pragma unroll
            for (int q = 0; q < 3; q++) {
                float2 wsh = ((const float2*)(W3s + (2 * j) * HID))[q * 32 + lane];
                float2 wsr = ((const float2*)(W3s + (2 * j + 1) * HID))[q * 32 + lane];
#pragma unroll
                for (int v = 0; v < 6; v++) {
                    accp[v][q] = ffma2(wsh, gv2[v], accp[v][q]);
                    accp[v][q] = ffma2(wsr, gf2[v], accp[v][q]);
                }
            }
        }

        // compact m2-active rows into gpair (capacity CAP2, exact overflow)
        int pre = 0;
#pragma unroll
        for (int g2 = 0; g2 < 6; g2++) pre += __popc(mm2[g2]);
        bool hasov = (pre > CAP2);
        unsigned ovm[6];
        int base2 = 0;
#pragma unroll
        for (int g2 = 0; g2 < 6; g2++) {
            int q = g2 >> 1, h = g2 & 1;
            unsigned m = mm2[g2], keep = m;
            if (hasov) {
                int pc = __popc(m);
                int ovc = base2 + pc - CAP2;
                if (ovc > 0) {
                    if (ovc > pc) ovc = pc;
                    for (int t = 0; t < ovc; t++) keep &= ~(0x80000000u >> __clz(keep));
                }
            }
            ovm[g2] = m ^ keep;
            if ((keep >> lane) & 1u) {
                int pos = base2 + __popc(keep & lt);
                gi[pos] = (unsigned short)(64 * q + 2 * lane + h);
                float g0 = h ? accp[0][q].y : accp[0][q].x;
                float g1 = h ? accp[1][q].y : accp[1][q].x;
                float g2v = h ? accp[2][q].y : accp[2][q].x;
                float g3 = h ? accp[3][q].y : accp[3][q].x;
                float g4 = h ? accp[4][q].y : accp[4][q].x;
                float g5 = h ? accp[5][q].y : accp[5][q].x;
                pw[pos * 3 + 0] = make_float2(g0, g1);
                pw[pos * 3 + 1] = make_float2(g2v, g3);
                pw[pos * 3 + 2] = make_float2(g4, g5);
            }
            base2 += __popc(keep);
        }
        int cnt2 = base2;
        __syncwarp();

        // main loop: 128 compacted output columns (t<4)
        float2 a1p[4][3];
#pragma unroll
        for (int t = 0; t < 4; t++)
#pragma unroll
            for (int p = 0; p < 3; p++) a1p[t][p] = make_float2(0.f, 0.f);
#pragma unroll 2
        for (int c = 0; c < cnt2; c++) {
            float2 g01 = pw[c * 3 + 0], g23 = pw[c * 3 + 1], g45 = pw[c * 3 + 2];
            int jj = gi[c];
            float wv0 = W2T[ccf[0] + jj];
            float wv1 = W2T[ccf[1] + jj];
            float wv2 = W2T[ccf[2] + jj];
            float wv3 = W2T[ccf[3] + jj];
            float2 w0 = make_float2(wv0, wv0), w1v = make_float2(wv1, wv1);
            float2 w2v = make_float2(wv2, wv2), w3v = make_float2(wv3, wv3);
            a1p[0][0] = ffma2(g01, w0, a1p[0][0]);
            a1p[0][1] = ffma2(g23, w0, a1p[0][1]);
            a1p[0][2] = ffma2(g45, w0, a1p[0][2]);
            a1p[1][0] = ffma2(g01, w1v, a1p[1][0]);
            a1p[1][1] = ffma2(g23, w1v, a1p[1][1]);
            a1p[1][2] = ffma2(g45, w1v, a1p[1][2]);
            a1p[2][0] = ffma2(g01, w2v, a1p[2][0]);
            a1p[2][1] = ffma2(g23, w2v, a1p[2][1]);
            a1p[2][2] = ffma2(g45, w2v, a1p[2][2]);
            a1p[3][0] = ffma2(g01, w3v, a1p[3][0]);
            a1p[3][1] = ffma2(g23, w3v, a1p[3][1]);
            a1p[3][2] = ffma2(g45, w3v, a1p[3][2]);
        }

        // tail: columns 128..cnt1 (ultra-rare)
        bool hastail = (cnt1 > 128);
        int co2[2]; bool t2v[2];
        float a1s0[6], a1s1[6];
        if (hastail) {
#pragma unroll
            for (int t2 = 0; t2 < 2; t2++) {
                int p = 128 + lane + 32 * t2;
                t2v[t2] = (p < cnt1);
                int cc = t2v[t2] ? (int)c1w[p] : 0;
                co2[t2] = cc * W2STR;
            }
#pragma unroll
            for (int v = 0; v < 6; v++) { a1s0[v] = 0.f; a1s1[v] = 0.f; }
            for (int c = 0; c < cnt2; c++) {
                float2 g01 = pw[c * 3 + 0], g23 = pw[c * 3 + 1], g45 = pw[c * 3 + 2];
                int jj = gi[c];
                float wa = W2T[co2[0] + jj], wbv = W2T[co2[1] + jj];
                a1s0[0] = fmaf(g01.x, wa, a1s0[0]); a1s0[1] = fmaf(g01.y, wa, a1s0[1]);
                a1s0[2] = fmaf(g23.x, wa, a1s0[2]); a1s0[3] = fmaf(g23.y, wa, a1s0[3]);
                a1s0[4] = fmaf(g45.x, wa, a1s0[4]); a1s0[5] = fmaf(g45.y, wa, a1s0[5]);
                a1s1[0] = fmaf(g01.x, wbv, a1s1[0]); a1s1[1] = fmaf(g01.y, wbv, a1s1[1]);
                a1s1[2] = fmaf(g23.x, wbv, a1s1[2]); a1s1[3] = fmaf(g23.y, wbv, a1s1[3]);
                a1s1[4] = fmaf(g45.x, wbv, a1s1[4]); a1s1[5] = fmaf(g45.y, wbv, a1s1[5]);
            }
        }

        // overflow fallback (exact; ultra-rare)
        if (hasov) {
#pragma unroll
            for (int g2 = 0; g2 < 6; g2++) {
                int q = g2 >> 1, h = g2 & 1;
                unsigned ov = ovm[g2];
                while (ov) {
                    int src = __ffs(ov) - 1; ov &= ov - 1;
                    float gg[6];
#pragma unroll
                    for (int v = 0; v < 6; v++) {
                        F2U u; u.f = accp[v][q];
                        u.u = __shfl_sync(0xffffffffu, u.u, src);
                        gg[v] = h ? u.f.y : u.f.x;
                    }
                    int cout = 64 * q + 2 * src + h;
#pragma unroll
                    for (int t = 0; t < 4; t++) {
                        float wv = W2T[ccf[t] + cout];
                        a1p[t][0].x = fmaf(gg[0], wv, a1p[t][0].x);
                        a1p[t][0].y = fmaf(gg[1], wv, a1p[t][0].y);
                        a1p[t][1].x = fmaf(gg[2], wv, a1p[t][1].x);
                        a1p[t][1].y = fmaf(gg[3], wv, a1p[t][1].y);
                        a1p[t][2].x = fmaf(gg[4], wv, a1p[t][2].x);
                        a1p[t][2].y = fmaf(gg[5], wv, a1p[t][2].y);
                    }
                    if (hastail) {
                        float wa = W2T[co2[0] + cout], wbv = W2T[co2[1] + cout];
#pragma unroll
                        for (int v = 0; v < 6; v++) {
                            a1s0[v] = fmaf(gg[v], wa, a1s0[v]);
                            a1s1[v] = fmaf(gg[v], wbv, a1s1[v]);
                        }
                    }
                }
            }
        }

        // fold a1 -> pz via W1 rows (columns are m1-active: no mask)
        float2 pzp[6][3];
#pragma unroll
        for (int v = 0; v < 6; v++)
#pragma unroll
            for (int jp = 0; jp < 3; jp++) pzp[v][jp] = make_float2(0.f, 0.f);
#pragma unroll
        for (int t = 0; t < 4; t++) {
            int p = lane + 32 * t;
            if (p < cmax) {
                int cc = (int)c1w[p];
                const float2* w1r = (const float2*)(W1s + cc * 6);
                float2 wA = w1r[0], wB = w1r[1], wC = w1r[2];
#pragma unroll
                for (int vp = 0; vp < 3; vp++) {
                    float a0 = a1p[t][vp].x, a1 = a1p[t][vp].y;
                    float2 a02 = make_float2(a0, a0), a12 = make_float2(a1, a1);
                    pzp[2 * vp][0]     = ffma2(wA, a02, pzp[2 * vp][0]);
                    pzp[2 * vp][1]     = ffma2(wB, a02, pzp[2 * vp][1]);
                    pzp[2 * vp][2]     = ffma2(wC, a02, pzp[2 * vp][2]);
                    pzp[2 * vp + 1][0] = ffma2(wA, a12, pzp[2 * vp + 1][0]);
                    pzp[2 * vp + 1][1] = ffma2(wB, a12, pzp[2 * vp + 1][1]);
                    pzp[2 * vp + 1][2] = ffma2(wC, a12, pzp[2 * vp + 1][2]);
                }
            }
        }
        if (hastail) {
#pragma unroll
            for (int t2 = 0; t2 < 2; t2++) {
                if (t2v[t2]) {
                    int cc = (int)c1w[128 + lane + 32 * t2];
                    const float* w1r = W1s + cc * 6;
                    const float* as = t2 ? a1s1 : a1s0;
#pragma unroll
                    for (int v = 0; v < 6; v++)
#pragma unroll
                        for (int jp = 0; jp < 3; jp++) {
                            pzp[v][jp].x = fmaf(as[v], w1r[2 * jp],     pzp[v][jp].x);
                            pzp[v][jp].y = fmaf(as[v], w1r[2 * jp + 1], pzp[v][jp].y);
                        }
                }
            }
        }

        // butterfly reduce (64-bit shuffles)
#pragma unroll
        for (int v = 0; v < 6; v++)
#pragma unroll
            for (int jp = 0; jp < 3; jp++) {
                F2U u; u.f = pzp[v][jp];
#pragma unroll
                for (int off = 16; off > 0; off >>= 1) {
                    F2U o2; o2.u = __shfl_xor_sync(0xffffffffu, u.u, off);
                    u.f.x += o2.f.x; u.f.y += o2.f.y;
                }
                pzp[v][jp] = u.f;
            }

        if (lane == 0) {
            float* vo = g_V + (size_t)b * 72;
#pragma unroll
            for (int v = 0; v < 6; v++)
#pragma unroll
                for (int j = 0; j < 6; j++) {
                    float pz = (j & 1) ? pzp[v][j >> 1].y : pzp[v][j >> 1].x;
                    vo[v * 12 + j]     = Vw[v * 12 + 6 + j] + pz;
                    vo[v * 12 + 6 + j] = Vw[v * 12 + j] * es[j];
                }
        }
    }
}

// ---------------- deterministic Frobenius-norm reduction ----------------
__global__ void k_ssq_part() {
    float s = 0.f;
    for (int i = blockIdx.x * blockDim.x + threadIdx.x; i < B * 72; i += gridDim.x * blockDim.x) {
        float v = g_V[i]; s += v * v;
    }
    __shared__ float red[256];
    red[threadIdx.x] = s; __syncthreads();
    for (int o = 128; o > 0; o >>= 1) {
        if (threadIdx.x < o) red[threadIdx.x] += red[threadIdx.x + o];
        __syncthreads();
    }
    if (threadIdx.x == 0) g_part[blockIdx.x] = red[0];
}
__global__ void k_ssq_final() {
    __shared__ float red[256];
    red[threadIdx.x] = g_part[threadIdx.x]; __syncthreads();
    for (int o = 128; o > 0; o >>= 1) {
        if (threadIdx.x < o) red[threadIdx.x] += red[threadIdx.x + o];
        __syncthreads();
    }
    if (threadIdx.x == 0) g_ssq = red[0];
}

// ---------------- KL + log_prob ----------------
#define LIX(r, c) ((r) * ((r) + 1) / 2 + (c))

__global__ void __launch_bounds__(64) k_kl(
    const float* __restrict__ Wsym, const float* __restrict__ lvd,
    float* __restrict__ out)
{
    __shared__ float As[NB * 144];
    for (int i = threadIdx.x; i < NB * 144; i += 64) {
        int m = i / 144; int rc = i % 144; int r = rc / 12; int c = rc % 12;
        As[i] = Wsym[m * 144 + r * 12 + c] - Wsym[m * 144 + c * 12 + r];
    }
    __syncthreads();

    int b = blockIdx.x * 64 + threadIdx.x;
    if (b >= B) return;

    float zr[12]; float zz = 0.f;
#pragma unroll
    for (int i = 0; i < 12; i++) { zr[i] = g_zk[(size_t)b * 12 + i]; zz += zr[i] * zr[i]; }
    out[b] = g_ld[b] - 6.f * 1.8378770664093453f - 0.5f * zz;

    float scale = rsqrtf(g_ssq);
    float Jp[6][12];
#pragma unroll
    for (int v = 0; v < 6; v++)
#pragma unroll
        for (int i = 0; i < 12; i++) Jp[v][i] = g_V[(size_t)b * 72 + v * 12 + i] * scale;

    float Sql[78];
#pragma unroll
    for (int i = 0; i < 78; i++) Sql[i] = 0.f;
    float trq = 0.f, trpq = 0.f;

    for (int m = 0; m < NB; m++) {
        const float* Am = As + m * 144;
        float Jq[12];
#pragma unroll
        for (int jj = 0; jj < 12; jj++) {
            float a = 0.f;
#pragma unroll
            for (int i = 0; i < 12; i++) a = fmaf(zr[i], Am[jj * 12 + i], a);
            Jq[jj] = a; trq = fmaf(a, a, trq);
        }
#pragma unroll
        for (int n = 0; n < 12; n++)
#pragma unroll
            for (int mm = 0; mm <= n; mm++) Sql[LIX(n, mm)] = fmaf(Jq[n], Jq[mm], Sql[LIX(n, mm)]);
#pragma unroll
        for (int v = 0; v < 6; v++) {
            float d = 0.f;
#pragma unroll
            for (int i = 0; i < 12; i++) d = fmaf(Jp[v][i], Jq[i], d);
            trpq = fmaf(d, d, trpq);
        }
    }

    float Ml[21];
#pragma unroll
    for (int a = 0; a < 6; a++)
#pragma unroll
        for (int c = 0; c <= a; c++) {
            float acc = 0.f;
#pragma unroll
            for (int i = 0; i < 12; i++) acc = fmaf(Jp[a][i], Jp[c][i], acc);
            Ml[LIX(a, c)] = acc;
        }
#pragma unroll
    for (int d = 0; d < 6; d++) Ml[LIX(d, d)] += 1e-3f;
    float dm = 0.f;
#pragma unroll
    for (int d = 0; d < 6; d++) dm += Ml[LIX(d, d)];
    float normM = fmaxf(dm * (1.f / 6.f), 1e-6f);
#pragma unroll
    for (int d = 0; d < 6; d++) Ml[LIX(d, d)] += 1e-3f * normM;

    float D[12];
#pragma unroll
    for (int i = 0; i < 12; i++) D[i] = expf(-lvd[i]);
#pragma unroll
    for (int d = 0; d < 12; d++) Sql[LIX(d, d)] += D[d];
    float dh = 0.f;
#pragma unroll
    for (int d = 0; d < 12; d++) dh += Sql[LIX(d, d)];
    float normH = fmaxf(dh * (1.f / 12.f), 1e-6f);
#pragma unroll
    for (int d = 0; d < 12; d++) Sql[LIX(d, d)] += 1e-3f * normH;

    float Db[12], sumDb = 0.f;
#pragma unroll
    for (int i = 0; i < 12; i++) { Db[i] = D[i] + 1e-3f * normH; sumDb += Db[i]; }

    float trp = 0.f;
#pragma unroll
    for (int v = 0; v < 6; v++)
#pragma unroll
        for (int i = 0; i < 12; i++) trp = fmaf(Jp[v][i] * Jp[v][i], Db[i], trp);

    float trace = (1e-3f + 1e-3f * normM) * (sumDb + trq) + trp + trpq;

    float ldM = 0.f;
#pragma unroll
    for (int c = 0; c < 6; c++) {
        float d = Ml[LIX(c, c)];
#pragma unroll
        for (int kk = 0; kk < c; kk++) d -= Ml[LIX(c, kk)] * Ml[LIX(c, kk)];
        d = sqrtf(d); ldM += 2.f * logf(d);
        float inv = 1.f / d;
#pragma unroll
        for (int r = c + 1; r < 6; r++) {
            float a = Ml[LIX(r, c)];
#pragma unroll
            for (int kk = 0; kk < c; kk++) a -= Ml[LIX(r, kk)] * Ml[LIX(c, kk)];
            Ml[LIX(r, c)] = a * inv;
        }
    }
    float ldH = 0.f;
#pragma unroll
    for (int c = 0; c < 12; c++) {
        float d = Sql[LIX(c, c)];
#pragma unroll
        for (int kk = 0; kk < c; kk++) d -= Sql[LIX(c, kk)] * Sql[LIX(c, kk)];
        d = sqrtf(d); ldH += 2.f * logf(d);
        float inv = 1.f / d;
#pragma unroll
        for (int r = c + 1; r < 12; r++) {
            float a = Sql[LIX(r, c)];
#pragma unroll
            for (int kk = 0; kk < c; kk++) a -= Sql[LIX(r, kk)] * Sql[LIX(c, kk)];
            Sql[LIX(r, c)] = a * inv;
        }
    }

    float logdet_p = ldM + 6.f * (-6.907755278982137f);
    out[B + b] = 0.5f * (trace - logdet_p - ldH - 12.f);
}

// ---------------- host launcher ----------------
extern "C" void kernel_launch(void* const* d_in, const int* in_sizes, int n_in,
                              void* d_out, int out_size) {
    const float* y    = (const float*)d_in[0];
    const float* Jp   = (const float*)d_in[1];
    const float* W1   = (const float*)d_in[2];
    const float* b1   = (const float*)d_in[3];
    const float* W2   = (const float*)d_in[4];
    const float* b2   = (const float*)d_in[5];
    const float* W3   = (const float*)d_in[6];
    const float* b3   = (const float*)d_in[7];
    const float* Wsym = (const float*)d_in[8];
    const float* lvd  = (const float*)d_in[9];
    float* out = (float*)d_out;

    const int SMEM_F = (OFF_WARP + 16 * WSTRIDE) * 4;  // 222,272 B
    cudaFuncSetAttribute(k_fused, cudaFuncAttributeMaxDynamicSharedMemorySize, SMEM_F);

    k_init<<<256, 256>>>(y, Jp);

    for (int k = LAYERS - 1; k >= 0; k--) {
        k_fused<<<152, 512, SMEM_F>>>(
            W1 + (size_t)k * HID * 6, b1 + (size_t)k * HID,
            W2 + (size_t)k * HID * HID, b2 + (size_t)k * HID,
            W3 + (size_t)k * 12 * HID,  b3 + (size_t)k * 12, k);
    }
    k_ssq_part<<<256, 256>>>();
    k_ssq_final<<<1, 256>>>();
    k_kl<<<(B + 63) / 64, 64>>>(Wsym, lvd, out);
}